// round 3
// baseline (speedup 1.0000x reference)
#include <cuda_runtime.h>
#include <math.h>

#define N_   512
#define B_   2
#define D_   128
#define O_   16
#define H_   64
#define CH_  48
#define NP_  514            // conv1 output spatial size (512 + 2*2 - 3 + 1)
#define SIXD 768
#define BD   (B_*D_)        // 256

// ---------------- scratch (static device arrays: allocation-rule safe) ------
__device__ float g_cum1[(N_+1)*BD];
__device__ float g_cum2[(N_+1)*BD];
__device__ float g_cum3[(N_+1)*BD];
__device__ float g_S0[B_*O_*N_*N_];      // [b][o][i][j]  (dense scatter target)
__device__ float g_H1[B_*CH_*NP_*NP_];   // [b][c][y][x]  conv1 output (gelu'd)

__device__ __forceinline__ float gelu_f(float v){
    return 0.5f * v * (1.0f + erff(v * 0.70710678118654752f));
}

// ---------------- prefix sums of x, x^2, x^3 with leading zero row ----------
__global__ void cumsum_kernel(const float* __restrict__ x){
    int t = threadIdx.x;            // 0..255 -> (b,d) flattened
    float s1 = 0.f, s2 = 0.f, s3 = 0.f;
    g_cum1[t] = 0.f; g_cum2[t] = 0.f; g_cum3[t] = 0.f;
    for (int n = 1; n <= N_; n++){
        float v = x[(n-1)*BD + t];
        s1 += v; s2 += v*v; s3 += v*v*v;
        int idx = n*BD + t;
        g_cum1[idx] = s1; g_cum2[idx] = s2; g_cum3[idx] = s3;
    }
}

// ---------------- zero the dense scatter buffer -----------------------------
__global__ void zero_S0(){
    int i = blockIdx.x*blockDim.x + threadIdx.x;
    int stride = gridDim.x*blockDim.x;
    float4* p = reinterpret_cast<float4*>(g_S0);
    const int n4 = (B_*O_*N_*N_)/4;
    for (; i < n4; i += stride) p[i] = make_float4(0.f,0.f,0.f,0.f);
}

// ---------------- pair MLP: one block = (row i, 64 j's, batch b) ------------
// smem (floats): sA 128 | sB 64*129 | sF 64*129 | sW 64*129    = 24896 floats
__global__ void pair_mlp_kernel(const float* __restrict__ x,
    const float* __restrict__ w1, const float* __restrict__ b1,
    const float* __restrict__ w2, const float* __restrict__ b2,
    const float* __restrict__ w3, const float* __restrict__ b3)
{
    extern __shared__ float sm[];
    float* sA = sm;               // 128   (x[i] row; reused for cum[i+1] row)
    float* sB = sm + 128;         // 64*129 (x[j] rows)
    float* sF = sB + 64*129;      // feature tile
    float* sW = sF + 64*129;      // weight tile

    const int tile = blockIdx.x;
    const int b    = blockIdx.y;
    // decode tile -> (i, jt).  Row group g (i in [64g,64g+63]) has g+1 tiles/row,
    // cumulative tiles before group g = 32*g*(g+1).
    int g = 0;
    while (g < 8 && 32*(g+1)*(g+2) <= tile) g++;
    const int rem = tile - 32*g*(g+1);
    const int i   = 64*g + rem/(g+1);
    const int j0  = (rem % (g+1)) * 64;

    const int t  = threadIdx.x;
    const int tr = t >> 4;        // 0..15 (row group of 4)
    const int tc = t & 15;        // 0..15 (col group of 4)

    if (t < 128) sA[t] = x[(i*B_ + b)*D_ + t];
    for (int idx = t; idx < 64*128; idx += 256){
        int r = idx >> 7, d = idx & 127;
        int j = j0 + r;
        sB[r*129 + d] = (j <= i) ? x[(j*B_ + b)*D_ + d] : 0.f;
    }
    __syncthreads();

    float acc[4][4];
    #pragma unroll
    for (int a = 0; a < 4; a++)
        #pragma unroll
        for (int q = 0; q < 4; q++) acc[a][q] = 0.f;

    // feature-block order: kb1 (=sB) last so sB stays live; sA reused from kb3 on
    const int order[6] = {0, 2, 3, 4, 5, 1};
    for (int s = 0; s < 6; s++){
        const int kb = order[s];
        if (s > 0) __syncthreads();                 // previous GEMM done
        for (int idx = t; idx < 64*128; idx += 256){
            int h = idx >> 7, d = idx & 127;
            sW[h*129 + d] = w1[h*SIXD + kb*128 + d];
        }
        const float* F = sF;
        if (kb == 0){
            for (int idx = t; idx < 64*128; idx += 256){
                int r = idx >> 7, d = idx & 127;
                sF[r*129 + d] = (j0 + r <= i) ? sA[d] : 0.f;
            }
        } else if (kb == 2){
            for (int idx = t; idx < 64*128; idx += 256){
                int r = idx >> 7, d = idx & 127;
                sF[r*129 + d] = sA[d] * sB[r*129 + d];
            }
        } else if (kb == 1){
            F = sB;
        } else {
            const float* cum = (kb == 3) ? g_cum1 : (kb == 4) ? g_cum2 : g_cum3;
            if (t < 128) sA[t] = cum[(i+1)*BD + b*D_ + t];
            __syncthreads();
            for (int idx = t; idx < 64*128; idx += 256){
                int r = idx >> 7, d = idx & 127;
                int j = j0 + r;
                if (j <= i){
                    float invL = 1.0f / (float)(i - j + 1);
                    sF[r*129 + d] = (sA[d] - cum[j*BD + b*D_ + d]) * invL;
                } else {
                    sF[r*129 + d] = 0.f;
                }
            }
        }
        __syncthreads();

        #pragma unroll 4
        for (int d = 0; d < 128; d++){
            float wv[4], fv[4];
            #pragma unroll
            for (int q = 0; q < 4; q++) wv[q] = sW[(tc*4 + q)*129 + d];
            #pragma unroll
            for (int a = 0; a < 4; a++) fv[a] = F[(tr*4 + a)*129 + d];
            #pragma unroll
            for (int a = 0; a < 4; a++)
                #pragma unroll
                for (int q = 0; q < 4; q++)
                    acc[a][q] += fv[a]*wv[q];
        }
    }
    __syncthreads();

    // ---- layer 2 ----
    float* sH  = sF;   // 64 x 65
    float* sW2 = sW;   // 64 x 65
    #pragma unroll
    for (int a = 0; a < 4; a++)
        #pragma unroll
        for (int q = 0; q < 4; q++){
            float v = acc[a][q] + b1[tc*4 + q];
            sH[(tr*4 + a)*65 + tc*4 + q] = gelu_f(v);
        }
    for (int idx = t; idx < 64*64; idx += 256){
        int h = idx >> 6, k = idx & 63;
        sW2[h*65 + k] = w2[h*64 + k];
    }
    __syncthreads();

    float acc2[4][4];
    #pragma unroll
    for (int a = 0; a < 4; a++)
        #pragma unroll
        for (int q = 0; q < 4; q++) acc2[a][q] = 0.f;
    #pragma unroll 4
    for (int k = 0; k < 64; k++){
        float wv[4], fv[4];
        #pragma unroll
        for (int q = 0; q < 4; q++) wv[q] = sW2[(tc*4 + q)*65 + k];
        #pragma unroll
        for (int a = 0; a < 4; a++) fv[a] = sH[(tr*4 + a)*65 + k];
        #pragma unroll
        for (int a = 0; a < 4; a++)
            #pragma unroll
            for (int q = 0; q < 4; q++)
                acc2[a][q] += fv[a]*wv[q];
    }

    // ---- layer 3 ----
    float* sH2 = sB;                // 64 x 65   (sB free now)
    float* sW3 = sW + 4224;         // 16 x 65   (past sW2's 4160 floats)
    #pragma unroll
    for (int a = 0; a < 4; a++)
        #pragma unroll
        for (int q = 0; q < 4; q++){
            float v = acc2[a][q] + b2[tc*4 + q];
            sH2[(tr*4 + a)*65 + tc*4 + q] = gelu_f(v);
        }
    for (int idx = t; idx < 16*64; idx += 256){
        int o = idx >> 6, k = idx & 63;
        sW3[o*65 + k] = w3[o*64 + k];
    }
    __syncthreads();

    const int r  = t & 63;
    const int og = t >> 6;          // 0..3 -> 4 output cols each
    const int j  = j0 + r;
    float acc3[4] = {0.f,0.f,0.f,0.f};
    #pragma unroll 4
    for (int k = 0; k < 64; k++){
        float hv = sH2[r*65 + k];
        #pragma unroll
        for (int q = 0; q < 4; q++) acc3[q] += hv * sW3[(og*4 + q)*65 + k];
    }
    if (j <= i){
        #pragma unroll
        for (int q = 0; q < 4; q++){
            int o = og*4 + q;
            g_S0[((b*O_ + o)*N_ + i)*N_ + j] = acc3[q] + b3[o];
        }
    }
}

// ---------------- conv1 (16->48, 3x3, pad=2) + gelu -------------------------
__global__ void conv1_kernel(const float* __restrict__ cw1, const float* __restrict__ cb1){
    __shared__ float sIn[16*324];      // 16 ch x 18x18 patch
    __shared__ float sWt[144*48];      // [o*9+kk][c]
    __shared__ float sBias[48];
    const int b  = blockIdx.z;
    const int y0 = blockIdx.y*16, x0 = blockIdx.x*16;
    const int tx = threadIdx.x, ty = threadIdx.y;
    const int t  = ty*16 + tx;

    for (int idx = t; idx < 48*144; idx += 256){
        int c = idx/144, rem = idx%144;            // rem = o*9 + kk
        sWt[rem*48 + c] = cw1[c*144 + rem];
    }
    if (t < 48) sBias[t] = cb1[t];
    for (int idx = t; idx < 16*324; idx += 256){
        int o = idx/324, p = idx%324;
        int py = p/18, px = p%18;
        int yy = y0 - 2 + py, xx = x0 - 2 + px;
        float v = 0.f;
        if (yy >= 0 && yy < N_ && xx >= 0 && xx < N_)
            v = g_S0[((b*O_ + o)*N_ + yy)*N_ + xx];
        sIn[o*324 + p] = v;
    }
    __syncthreads();

    float acc[48];
    #pragma unroll
    for (int c = 0; c < 48; c++) acc[c] = sBias[c];
    for (int o = 0; o < 16; o++){
        #pragma unroll
        for (int ky = 0; ky < 3; ky++)
            #pragma unroll
            for (int kx = 0; kx < 3; kx++){
                float v = sIn[o*324 + (ty+ky)*18 + tx + kx];
                const float4* wp = reinterpret_cast<const float4*>(&sWt[(o*9 + ky*3 + kx)*48]);
                #pragma unroll
                for (int c4 = 0; c4 < 12; c4++){
                    float4 w4 = wp[c4];
                    acc[c4*4+0] += v*w4.x; acc[c4*4+1] += v*w4.y;
                    acc[c4*4+2] += v*w4.z; acc[c4*4+3] += v*w4.w;
                }
            }
    }
    const int y = y0 + ty, x = x0 + tx;
    if (y < NP_ && x < NP_){
        #pragma unroll
        for (int c = 0; c < 48; c++)
            g_H1[((b*CH_ + c)*NP_ + y)*NP_ + x] = gelu_f(acc[c]);
    }
}

// ------- conv2 (48->16, 3x3, valid) + bias + |i-j| scale + permute ----------
__global__ void conv2_kernel(const float* __restrict__ cw2, const float* __restrict__ cb2,
                             float* __restrict__ out){
    extern __shared__ float sm[];
    float* sIn   = sm;                 // 48 x 18x18
    float* sWt   = sm + 48*324;        // [c*9+kk][o]
    float* sBias = sWt + 432*16;       // 16
    const int b  = blockIdx.z;
    const int y0 = blockIdx.y*16, x0 = blockIdx.x*16;
    const int tx = threadIdx.x, ty = threadIdx.y;
    const int t  = ty*16 + tx;

    for (int idx = t; idx < 16*432; idx += 256){
        int o = idx/432, rem = idx%432;            // rem = c*9 + kk
        sWt[rem*16 + o] = cw2[o*432 + rem];
    }
    if (t < 16) sBias[t] = cb2[t];
    for (int idx = t; idx < 48*324; idx += 256){
        int c = idx/324, p = idx%324;
        int py = p/18, px = p%18;
        sIn[c*324 + p] = g_H1[((b*CH_ + c)*NP_ + y0 + py)*NP_ + x0 + px];
    }
    __syncthreads();

    float acc[16];
    #pragma unroll
    for (int o = 0; o < 16; o++) acc[o] = sBias[o];
    for (int c = 0; c < 48; c++){
        #pragma unroll
        for (int ky = 0; ky < 3; ky++)
            #pragma unroll
            for (int kx = 0; kx < 3; kx++){
                float v = sIn[c*324 + (ty+ky)*18 + tx + kx];
                const float4* wp = reinterpret_cast<const float4*>(&sWt[(c*9 + ky*3 + kx)*16]);
                #pragma unroll
                for (int o4 = 0; o4 < 4; o4++){
                    float4 w4 = wp[o4];
                    acc[o4*4+0] += v*w4.x; acc[o4*4+1] += v*w4.y;
                    acc[o4*4+2] += v*w4.z; acc[o4*4+3] += v*w4.w;
                }
            }
    }
    const int y = y0 + ty, x = x0 + tx;          // always < 512
    int diff = y - x; if (diff < 0) diff = -diff; if (diff < 1) diff = 1;
    const float len = (float)diff;
    float4* op = reinterpret_cast<float4*>(&out[((y*N_ + x)*B_ + b)*O_]);
    #pragma unroll
    for (int o4 = 0; o4 < 4; o4++)
        op[o4] = make_float4(len*acc[o4*4+0], len*acc[o4*4+1],
                             len*acc[o4*4+2], len*acc[o4*4+3]);
}

// ---------------- skip MLP on adjacent frames -------------------------------
__global__ void skip_kernel(const float* __restrict__ x,
    const float* __restrict__ sw1, const float* __restrict__ sb1,
    const float* __restrict__ sw2, const float* __restrict__ sb2,
    const float* __restrict__ sw3, const float* __restrict__ sb3,
    float* __restrict__ out){
    __shared__ float sFeat[384];
    __shared__ float sH1[64];
    __shared__ float sH2[64];
    const int i = blockIdx.x, b = blockIdx.y;
    const int t = threadIdx.x;   // 128
    {
        float xa = x[(i*B_ + b)*D_ + t];
        float xb = x[((i+1)*B_ + b)*D_ + t];
        sFeat[t] = xa; sFeat[128 + t] = xb; sFeat[256 + t] = xa*xb;
    }
    __syncthreads();
    if (t < 64){
        float a = sb1[t];
        #pragma unroll 4
        for (int k = 0; k < 384; k++) a += sFeat[k]*sw1[t*384 + k];
        sH1[t] = gelu_f(a);
    }
    __syncthreads();
    if (t < 64){
        float a = sb2[t];
        #pragma unroll 4
        for (int k = 0; k < 64; k++) a += sH1[k]*sw2[t*64 + k];
        sH2[t] = gelu_f(a);
    }
    __syncthreads();
    if (t < 16){
        float a = sb3[t];
        #pragma unroll 4
        for (int k = 0; k < 64; k++) a += sH2[k]*sw3[t*64 + k];
        out[(i*B_ + b)*O_ + t] = a;
    }
}

// ---------------------------------------------------------------------------
extern "C" void kernel_launch(void* const* d_in, const int* in_sizes, int n_in,
                              void* d_out, int out_size){
    const float* x   = (const float*)d_in[0];
    const float* w1  = (const float*)d_in[1];
    const float* b1  = (const float*)d_in[2];
    const float* w2  = (const float*)d_in[3];
    const float* b2  = (const float*)d_in[4];
    const float* w3  = (const float*)d_in[5];
    const float* b3  = (const float*)d_in[6];
    const float* sw1 = (const float*)d_in[7];
    const float* sb1 = (const float*)d_in[8];
    const float* sw2 = (const float*)d_in[9];
    const float* sb2 = (const float*)d_in[10];
    const float* sw3 = (const float*)d_in[11];
    const float* sb3 = (const float*)d_in[12];
    const float* cw1 = (const float*)d_in[13];
    const float* cb1 = (const float*)d_in[14];
    const float* cw2 = (const float*)d_in[15];
    const float* cb2 = (const float*)d_in[16];
    float* out = (float*)d_out;

    const int mlp_smem = 24896*4;     // 99,584 B
    const int c2_smem  = (48*324 + 432*16 + 16)*4;  // 89,920 B
    cudaFuncSetAttribute(pair_mlp_kernel, cudaFuncAttributeMaxDynamicSharedMemorySize, mlp_smem);
    cudaFuncSetAttribute(conv2_kernel,    cudaFuncAttributeMaxDynamicSharedMemorySize, c2_smem);

    cumsum_kernel<<<1, 256>>>(x);
    zero_S0<<<2048, 256>>>();

    dim3 gC(2304, 2);
    pair_mlp_kernel<<<gC, 256, mlp_smem>>>(x, w1, b1, w2, b2, w3, b3);

    dim3 blk(16, 16);
    conv1_kernel<<<dim3(33, 33, 2), blk>>>(cw1, cb1);
    conv2_kernel<<<dim3(32, 32, 2), blk, c2_smem>>>(cw2, cb2, out);

    skip_kernel<<<dim3(N_-1, 2), 128>>>(x, sw1, sb1, sw2, sb2, sw3, sb3,
                                        out + (size_t)N_*N_*B_*O_);
}

// round 5
// speedup vs baseline: 1.6148x; 1.6148x over previous
#include <cuda_runtime.h>
#include <math.h>
#include <stdint.h>

#define N_   512
#define B_   2
#define D_   128
#define O_   16
#define H_   64
#define CH_  48
#define NP_  514
#define SIXD 768
#define BD   (B_*D_)        // 256

// ---------------- scratch ----------------------------------------------------
__device__ float g_cum1[(N_+1)*BD];
__device__ float g_cum2[(N_+1)*BD];
__device__ float g_cum3[(N_+1)*BD];
__device__ float g_S0[B_*O_*N_*N_];      // [b][o][i][j]
__device__ float g_H1[B_*CH_*NP_*NP_];   // [b][c][y][x]

__device__ __forceinline__ float gelu_f(float v){
    return 0.5f * v * (1.0f + erff(v * 0.70710678118654752f));
}

__device__ __forceinline__ uint32_t f2tf32(float v){
    uint32_t r;
    asm("cvt.rna.tf32.f32 %0, %1;" : "=r"(r) : "f"(v));
    return r;
}

__device__ __forceinline__ void mma_tf32(float* c,
    uint32_t a0, uint32_t a1, uint32_t a2, uint32_t a3, uint32_t b0, uint32_t b1)
{
    asm volatile(
        "mma.sync.aligned.m16n8k8.row.col.f32.tf32.tf32.f32 "
        "{%0,%1,%2,%3}, {%4,%5,%6,%7}, {%8,%9}, {%0,%1,%2,%3};"
        : "+f"(c[0]), "+f"(c[1]), "+f"(c[2]), "+f"(c[3])
        : "r"(a0), "r"(a1), "r"(a2), "r"(a3), "r"(b0), "r"(b1));
}

// ---------------- prefix sums ------------------------------------------------
__global__ void cumsum_kernel(const float* __restrict__ x){
    int t = threadIdx.x;
    float s1 = 0.f, s2 = 0.f, s3 = 0.f;
    g_cum1[t] = 0.f; g_cum2[t] = 0.f; g_cum3[t] = 0.f;
    for (int n = 1; n <= N_; n++){
        float v = x[(n-1)*BD + t];
        s1 += v; s2 += v*v; s3 += v*v*v;
        int idx = n*BD + t;
        g_cum1[idx] = s1; g_cum2[idx] = s2; g_cum3[idx] = s3;
    }
}

__global__ void zero_S0(){
    int i = blockIdx.x*blockDim.x + threadIdx.x;
    int stride = gridDim.x*blockDim.x;
    float4* p = reinterpret_cast<float4*>(g_S0);
    const int n4 = (B_*O_*N_*N_)/4;
    for (; i < n4; i += stride) p[i] = make_float4(0.f,0.f,0.f,0.f);
}

// ---------------- pair MLP on mma.sync tf32 ----------------------------------
// Tile: 128 pairs (row i, j0..j0+127) x batch b.  256 threads = 8 warps,
// warp w owns output rows [16w, 16w+16).  Layer widths: 768->64->64->16.
// SMEM float offsets:
#define SF_F    0        // feature / hidden tile: 128 x 132 (layer1) or x 68
#define SW_F    16896    // weight tile: 64 x 132
#define XI_F    25344    // x[i] row (128)
#define C1_F    25472
#define C2_F    25600
#define C3_F    25728
#define B1_F    25856
#define B2_F    25920
#define B3_F    25984
#define INVL_F  26000    // per-row 1/L (128)
#define PAIR_SMEM_F 26128
#define PAIR_SMEM_BYTES (PAIR_SMEM_F*4)

__global__ void __launch_bounds__(256)
pair_mlp_mma(const float* __restrict__ x,
    const float* __restrict__ w1, const float* __restrict__ b1,
    const float* __restrict__ w2, const float* __restrict__ b2,
    const float* __restrict__ w3, const float* __restrict__ b3)
{
    extern __shared__ float sm[];
    float* sF = sm + SF_F;
    float* sW = sm + SW_F;

    const int t    = threadIdx.x;
    const int warp = t >> 5;
    const int lane = t & 31;
    const int qrow = lane >> 2;      // 0..7
    const int qcol = lane & 3;       // 0..3
    const int r0   = warp*16 + qrow; // A-fragment base row

    const int tile = blockIdx.x;
    const int b    = blockIdx.y;
    const int g    = (tile >= 768) ? 3 : (tile >= 384) ? 2 : (tile >= 128) ? 1 : 0;
    const int rem  = tile - 64*g*(g+1);
    const int i    = 128*g + rem/(g+1);
    const int j0   = 128*(rem % (g+1));

    // stage broadcast rows, biases, per-row invL
    if (t < 128){
        sm[XI_F + t] = x[(i*B_ + b)*D_ + t];
        sm[C1_F + t] = g_cum1[(i+1)*BD + b*D_ + t];
        sm[C2_F + t] = g_cum2[(i+1)*BD + b*D_ + t];
        sm[C3_F + t] = g_cum3[(i+1)*BD + b*D_ + t];
        int j = j0 + t;
        sm[INVL_F + t] = (j <= i) ? 1.0f/(float)(i - j + 1) : 0.0f;
    }
    if (t < 64){ sm[B1_F + t] = b1[t]; sm[B2_F + t] = b2[t]; }
    if (t < 16){ sm[B3_F + t] = b3[t]; }

    float acc[32];
    #pragma unroll
    for (int q = 0; q < 32; q++) acc[q] = 0.f;

    // ---------------- layer 1: 6 feature chunks of K=128 --------------------
    for (int c = 0; c < 6; c++){
        __syncthreads();   // staged data visible / prior mma reads complete

        // stage W1 chunk (64 x 128), converted to tf32
        for (int idx = t; idx < 64*128; idx += 256){
            int h = idx >> 7, d = idx & 127;
            sW[h*132 + d] = __uint_as_float(f2tf32(w1[h*SIXD + c*128 + d]));
        }
        // build feature tile (128 x 128), converted to tf32
        if (c == 0){
            for (int idx = t; idx < 128*128; idx += 256){
                int r = idx >> 7, d = idx & 127;
                float v = (j0 + r <= i) ? sm[XI_F + d] : 0.f;
                sF[r*132 + d] = __uint_as_float(f2tf32(v));
            }
        } else if (c == 1){
            for (int idx = t; idx < 128*128; idx += 256){
                int r = idx >> 7, d = idx & 127;
                int j = j0 + r;
                float v = (j <= i) ? x[(j*B_ + b)*D_ + d] : 0.f;
                sF[r*132 + d] = __uint_as_float(f2tf32(v));
            }
        } else if (c == 2){
            for (int idx = t; idx < 128*128; idx += 256){
                int r = idx >> 7, d = idx & 127;
                int j = j0 + r;
                float v = (j <= i) ? sm[XI_F + d]*x[(j*B_ + b)*D_ + d] : 0.f;
                sF[r*132 + d] = __uint_as_float(f2tf32(v));
            }
        } else {
            const float* cumg = (c == 3) ? g_cum1 : (c == 4) ? g_cum2 : g_cum3;
            const float* cs   = sm + ((c == 3) ? C1_F : (c == 4) ? C2_F : C3_F);
            for (int idx = t; idx < 128*128; idx += 256){
                int r = idx >> 7, d = idx & 127;
                int j = j0 + r;
                float v = (cs[d] - cumg[j*BD + b*D_ + d]) * sm[INVL_F + r];
                sF[r*132 + d] = __uint_as_float(f2tf32(v));
            }
        }
        __syncthreads();

        #pragma unroll
        for (int ks = 0; ks < 16; ks++){
            const int kb = ks*8;
            uint32_t a0 = __float_as_uint(sF[(r0    )*132 + kb + qcol    ]);
            uint32_t a1 = __float_as_uint(sF[(r0 + 8)*132 + kb + qcol    ]);
            uint32_t a2 = __float_as_uint(sF[(r0    )*132 + kb + qcol + 4]);
            uint32_t a3 = __float_as_uint(sF[(r0 + 8)*132 + kb + qcol + 4]);
            #pragma unroll
            for (int nt = 0; nt < 8; nt++){
                uint32_t b0 = __float_as_uint(sW[(nt*8 + qrow)*132 + kb + qcol    ]);
                uint32_t b1v= __float_as_uint(sW[(nt*8 + qrow)*132 + kb + qcol + 4]);
                mma_tf32(acc + nt*4, a0, a1, a2, a3, b0, b1v);
            }
        }
    }
    __syncthreads();   // all layer-1 mma done: sF/sW reusable

    // ---------------- layer 1 epilogue: bias + gelu -> sH (stride 68) -------
    #pragma unroll
    for (int nt = 0; nt < 8; nt++){
        const int col = nt*8 + qcol*2;
        float v0 = gelu_f(acc[nt*4+0] + sm[B1_F + col    ]);
        float v1 = gelu_f(acc[nt*4+1] + sm[B1_F + col + 1]);
        float v2 = gelu_f(acc[nt*4+2] + sm[B1_F + col    ]);
        float v3 = gelu_f(acc[nt*4+3] + sm[B1_F + col + 1]);
        sF[(r0    )*68 + col    ] = __uint_as_float(f2tf32(v0));
        sF[(r0    )*68 + col + 1] = __uint_as_float(f2tf32(v1));
        sF[(r0 + 8)*68 + col    ] = __uint_as_float(f2tf32(v2));
        sF[(r0 + 8)*68 + col + 1] = __uint_as_float(f2tf32(v3));
    }
    // stage W2 (64 x 64)
    for (int idx = t; idx < 64*64; idx += 256){
        int h = idx >> 6, k = idx & 63;
        sW[h*132 + k] = __uint_as_float(f2tf32(w2[h*64 + k]));
    }
    __syncthreads();

    // ---------------- layer 2 -------------------------------------------------
    #pragma unroll
    for (int q = 0; q < 32; q++) acc[q] = 0.f;
    #pragma unroll
    for (int ks = 0; ks < 8; ks++){
        const int kb = ks*8;
        uint32_t a0 = __float_as_uint(sF[(r0    )*68 + kb + qcol    ]);
        uint32_t a1 = __float_as_uint(sF[(r0 + 8)*68 + kb + qcol    ]);
        uint32_t a2 = __float_as_uint(sF[(r0    )*68 + kb + qcol + 4]);
        uint32_t a3 = __float_as_uint(sF[(r0 + 8)*68 + kb + qcol + 4]);
        #pragma unroll
        for (int nt = 0; nt < 8; nt++){
            uint32_t b0 = __float_as_uint(sW[(nt*8 + qrow)*132 + kb + qcol    ]);
            uint32_t b1v= __float_as_uint(sW[(nt*8 + qrow)*132 + kb + qcol + 4]);
            mma_tf32(acc + nt*4, a0, a1, a2, a3, b0, b1v);
        }
    }
    __syncthreads();   // layer-2 mma done

    // ---------------- layer 2 epilogue -> sH2, stage W3 -----------------------
    #pragma unroll
    for (int nt = 0; nt < 8; nt++){
        const int col = nt*8 + qcol*2;
        float v0 = gelu_f(acc[nt*4+0] + sm[B2_F + col    ]);
        float v1 = gelu_f(acc[nt*4+1] + sm[B2_F + col + 1]);
        float v2 = gelu_f(acc[nt*4+2] + sm[B2_F + col    ]);
        float v3 = gelu_f(acc[nt*4+3] + sm[B2_F + col + 1]);
        sF[(r0    )*68 + col    ] = __uint_as_float(f2tf32(v0));
        sF[(r0    )*68 + col + 1] = __uint_as_float(f2tf32(v1));
        sF[(r0 + 8)*68 + col    ] = __uint_as_float(f2tf32(v2));
        sF[(r0 + 8)*68 + col + 1] = __uint_as_float(f2tf32(v3));
    }
    for (int idx = t; idx < 16*64; idx += 256){
        int h = idx >> 6, k = idx & 63;
        sW[h*132 + k] = __uint_as_float(f2tf32(w3[h*64 + k]));
    }
    __syncthreads();

    // ---------------- layer 3 (N=16) ------------------------------------------
    float acc3[8];
    #pragma unroll
    for (int q = 0; q < 8; q++) acc3[q] = 0.f;
    #pragma unroll
    for (int ks = 0; ks < 8; ks++){
        const int kb = ks*8;
        uint32_t a0 = __float_as_uint(sF[(r0    )*68 + kb + qcol    ]);
        uint32_t a1 = __float_as_uint(sF[(r0 + 8)*68 + kb + qcol    ]);
        uint32_t a2 = __float_as_uint(sF[(r0    )*68 + kb + qcol + 4]);
        uint32_t a3 = __float_as_uint(sF[(r0 + 8)*68 + kb + qcol + 4]);
        #pragma unroll
        for (int nt = 0; nt < 2; nt++){
            uint32_t b0 = __float_as_uint(sW[(nt*8 + qrow)*132 + kb + qcol    ]);
            uint32_t b1v= __float_as_uint(sW[(nt*8 + qrow)*132 + kb + qcol + 4]);
            mma_tf32(acc3 + nt*4, a0, a1, a2, a3, b0, b1v);
        }
    }

    // ---------------- final scatter into g_S0 ---------------------------------
    #pragma unroll
    for (int nt = 0; nt < 2; nt++){
        #pragma unroll
        for (int e = 0; e < 4; e++){
            const int o   = nt*8 + qcol*2 + (e & 1);
            const int row = r0 + ((e >= 2) ? 8 : 0);
            const int j   = j0 + row;
            if (j <= i)
                g_S0[((b*O_ + o)*N_ + i)*N_ + j] = acc3[nt*4 + e] + sm[B3_F + o];
        }
    }
}

// ---------------- conv1 (16->48, 3x3, pad=2) + gelu -------------------------
__global__ void conv1_kernel(const float* __restrict__ cw1, const float* __restrict__ cb1){
    __shared__ float sIn[16*324];
    __shared__ float sWt[144*48];
    __shared__ float sBias[48];
    const int b  = blockIdx.z;
    const int y0 = blockIdx.y*16, x0 = blockIdx.x*16;
    const int tx = threadIdx.x, ty = threadIdx.y;
    const int t  = ty*16 + tx;

    for (int idx = t; idx < 48*144; idx += 256){
        int c = idx/144, rem = idx%144;
        sWt[rem*48 + c] = cw1[c*144 + rem];
    }
    if (t < 48) sBias[t] = cb1[t];
    for (int idx = t; idx < 16*324; idx += 256){
        int o = idx/324, p = idx%324;
        int py = p/18, px = p%18;
        int yy = y0 - 2 + py, xx = x0 - 2 + px;
        float v = 0.f;
        if (yy >= 0 && yy < N_ && xx >= 0 && xx < N_)
            v = g_S0[((b*O_ + o)*N_ + yy)*N_ + xx];
        sIn[o*324 + p] = v;
    }
    __syncthreads();

    float acc[48];
    #pragma unroll
    for (int c = 0; c < 48; c++) acc[c] = sBias[c];
    for (int o = 0; o < 16; o++){
        #pragma unroll
        for (int ky = 0; ky < 3; ky++)
            #pragma unroll
            for (int kx = 0; kx < 3; kx++){
                float v = sIn[o*324 + (ty+ky)*18 + tx + kx];
                const float4* wp = reinterpret_cast<const float4*>(&sWt[(o*9 + ky*3 + kx)*48]);
                #pragma unroll
                for (int c4 = 0; c4 < 12; c4++){
                    float4 w4 = wp[c4];
                    acc[c4*4+0] += v*w4.x; acc[c4*4+1] += v*w4.y;
                    acc[c4*4+2] += v*w4.z; acc[c4*4+3] += v*w4.w;
                }
            }
    }
    const int y = y0 + ty, x = x0 + tx;
    if (y < NP_ && x < NP_){
        #pragma unroll
        for (int c = 0; c < 48; c++)
            g_H1[((b*CH_ + c)*NP_ + y)*NP_ + x] = gelu_f(acc[c]);
    }
}

// ------- conv2 (48->16, 3x3, valid) + bias + |i-j| scale + permute ----------
__global__ void conv2_kernel(const float* __restrict__ cw2, const float* __restrict__ cb2,
                             float* __restrict__ out){
    extern __shared__ float smv[];
    float* sIn   = smv;
    float* sWt   = smv + 48*324;
    float* sBias = sWt + 432*16;
    const int b  = blockIdx.z;
    const int y0 = blockIdx.y*16, x0 = blockIdx.x*16;
    const int tx = threadIdx.x, ty = threadIdx.y;
    const int t  = ty*16 + tx;

    for (int idx = t; idx < 16*432; idx += 256){
        int o = idx/432, rem = idx%432;
        sWt[rem*16 + o] = cw2[o*432 + rem];
    }
    if (t < 16) sBias[t] = cb2[t];
    for (int idx = t; idx < 48*324; idx += 256){
        int c = idx/324, p = idx%324;
        int py = p/18, px = p%18;
        sIn[c*324 + p] = g_H1[((b*CH_ + c)*NP_ + y0 + py)*NP_ + x0 + px];
    }
    __syncthreads();

    float acc[16];
    #pragma unroll
    for (int o = 0; o < 16; o++) acc[o] = sBias[o];
    for (int c = 0; c < 48; c++){
        #pragma unroll
        for (int ky = 0; ky < 3; ky++)
            #pragma unroll
            for (int kx = 0; kx < 3; kx++){
                float v = sIn[c*324 + (ty+ky)*18 + tx + kx];
                const float4* wp = reinterpret_cast<const float4*>(&sWt[(c*9 + ky*3 + kx)*16]);
                #pragma unroll
                for (int o4 = 0; o4 < 4; o4++){
                    float4 w4 = wp[o4];
                    acc[o4*4+0] += v*w4.x; acc[o4*4+1] += v*w4.y;
                    acc[o4*4+2] += v*w4.z; acc[o4*4+3] += v*w4.w;
                }
            }
    }
    const int y = y0 + ty, x = x0 + tx;
    int diff = y - x; if (diff < 0) diff = -diff; if (diff < 1) diff = 1;
    const float len = (float)diff;
    float4* op = reinterpret_cast<float4*>(&out[((y*N_ + x)*B_ + b)*O_]);
    #pragma unroll
    for (int o4 = 0; o4 < 4; o4++)
        op[o4] = make_float4(len*acc[o4*4+0], len*acc[o4*4+1],
                             len*acc[o4*4+2], len*acc[o4*4+3]);
}

// ---------------- skip MLP ---------------------------------------------------
__global__ void skip_kernel(const float* __restrict__ x,
    const float* __restrict__ sw1, const float* __restrict__ sb1,
    const float* __restrict__ sw2, const float* __restrict__ sb2,
    const float* __restrict__ sw3, const float* __restrict__ sb3,
    float* __restrict__ out){
    __shared__ float sFeat[384];
    __shared__ float sH1[64];
    __shared__ float sH2[64];
    const int i = blockIdx.x, b = blockIdx.y;
    const int t = threadIdx.x;
    {
        float xa = x[(i*B_ + b)*D_ + t];
        float xb = x[((i+1)*B_ + b)*D_ + t];
        sFeat[t] = xa; sFeat[128 + t] = xb; sFeat[256 + t] = xa*xb;
    }
    __syncthreads();
    if (t < 64){
        float a = sb1[t];
        #pragma unroll 4
        for (int k = 0; k < 384; k++) a += sFeat[k]*sw1[t*384 + k];
        sH1[t] = gelu_f(a);
    }
    __syncthreads();
    if (t < 64){
        float a = sb2[t];
        #pragma unroll 4
        for (int k = 0; k < 64; k++) a += sH1[k]*sw2[t*64 + k];
        sH2[t] = gelu_f(a);
    }
    __syncthreads();
    if (t < 16){
        float a = sb3[t];
        #pragma unroll 4
        for (int k = 0; k < 64; k++) a += sH2[k]*sw3[t*64 + k];
        out[(i*B_ + b)*O_ + t] = a;
    }
}

// ---------------------------------------------------------------------------
extern "C" void kernel_launch(void* const* d_in, const int* in_sizes, int n_in,
                              void* d_out, int out_size){
    const float* x   = (const float*)d_in[0];
    const float* w1  = (const float*)d_in[1];
    const float* b1  = (const float*)d_in[2];
    const float* w2  = (const float*)d_in[3];
    const float* b2  = (const float*)d_in[4];
    const float* w3  = (const float*)d_in[5];
    const float* b3  = (const float*)d_in[6];
    const float* sw1 = (const float*)d_in[7];
    const float* sb1 = (const float*)d_in[8];
    const float* sw2 = (const float*)d_in[9];
    const float* sb2 = (const float*)d_in[10];
    const float* sw3 = (const float*)d_in[11];
    const float* sb3 = (const float*)d_in[12];
    const float* cw1 = (const float*)d_in[13];
    const float* cb1 = (const float*)d_in[14];
    const float* cw2 = (const float*)d_in[15];
    const float* cb2 = (const float*)d_in[16];
    float* out = (float*)d_out;

    const int c2_smem = (48*324 + 432*16 + 16)*4;
    cudaFuncSetAttribute(pair_mlp_mma, cudaFuncAttributeMaxDynamicSharedMemorySize, PAIR_SMEM_BYTES);
    cudaFuncSetAttribute(conv2_kernel, cudaFuncAttributeMaxDynamicSharedMemorySize, c2_smem);

    cumsum_kernel<<<1, 256>>>(x);
    zero_S0<<<2048, 256>>>();

    pair_mlp_mma<<<dim3(1280, 2), 256, PAIR_SMEM_BYTES>>>(x, w1, b1, w2, b2, w3, b3);

    dim3 blk(16, 16);
    conv1_kernel<<<dim3(33, 33, 2), blk>>>(cw1, cb1);
    conv2_kernel<<<dim3(32, 32, 2), blk, c2_smem>>>(cw2, cb2, out);

    skip_kernel<<<dim3(N_-1, 2), 128>>>(x, sw1, sb1, sw2, sb2, sw3, sb3,
                                        out + (size_t)N_*N_*B_*O_);
}

// round 6
// speedup vs baseline: 1.6212x; 1.0040x over previous
#include <cuda_runtime.h>
#include <math.h>
#include <stdint.h>

#define N_   512
#define B_   2
#define D_   128
#define O_   16
#define H_   64
#define CH_  48
#define NP_  514
#define SIXD 768
#define BD   (B_*D_)        // 256

// ---------------- scratch ----------------------------------------------------
__device__ float g_cum1[(N_+1)*BD];
__device__ float g_cum2[(N_+1)*BD];
__device__ float g_cum3[(N_+1)*BD];
__device__ float g_S0[B_*O_*N_*N_];      // [b][o][i][j]
__device__ float g_H1[B_*CH_*NP_*NP_];   // [b][c][y][x]

__device__ __forceinline__ float gelu_f(float v){
    return 0.5f * v * (1.0f + erff(v * 0.70710678118654752f));
}

__device__ __forceinline__ uint32_t f2tf32(float v){
    uint32_t r;
    asm("cvt.rna.tf32.f32 %0, %1;" : "=r"(r) : "f"(v));
    return r;
}

__device__ __forceinline__ void mma_tf32(float* c,
    uint32_t a0, uint32_t a1, uint32_t a2, uint32_t a3, uint32_t b0, uint32_t b1)
{
    asm volatile(
        "mma.sync.aligned.m16n8k8.row.col.f32.tf32.tf32.f32 "
        "{%0,%1,%2,%3}, {%4,%5,%6,%7}, {%8,%9}, {%0,%1,%2,%3};"
        : "+f"(c[0]), "+f"(c[1]), "+f"(c[2]), "+f"(c[3])
        : "r"(a0), "r"(a1), "r"(a2), "r"(a3), "r"(b0), "r"(b1));
}

// ---------------- prefix sums ------------------------------------------------
__global__ void cumsum_kernel(const float* __restrict__ x){
    int t = threadIdx.x;
    float s1 = 0.f, s2 = 0.f, s3 = 0.f;
    g_cum1[t] = 0.f; g_cum2[t] = 0.f; g_cum3[t] = 0.f;
    for (int n = 1; n <= N_; n++){
        float v = x[(n-1)*BD + t];
        s1 += v; s2 += v*v; s3 += v*v*v;
        int idx = n*BD + t;
        g_cum1[idx] = s1; g_cum2[idx] = s2; g_cum3[idx] = s3;
    }
}

__global__ void zero_S0(){
    int i = blockIdx.x*blockDim.x + threadIdx.x;
    int stride = gridDim.x*blockDim.x;
    float4* p = reinterpret_cast<float4*>(g_S0);
    const int n4 = (B_*O_*N_*N_)/4;
    for (; i < n4; i += stride) p[i] = make_float4(0.f,0.f,0.f,0.f);
}

// ---------------- pair MLP on mma.sync tf32 (restructured) -------------------
// SMEM float offsets:
#define SF_F    0        // feature / hidden tile: 128 x 132 (layer1) or x 68
#define SW_F    16896    // weight tile: 64 x 132
#define XI_F    25344    // x[i] row (128)
#define C1_F    25472
#define C2_F    25600
#define C3_F    25728
#define B1_F    25856
#define B2_F    25920
#define B3_F    25984
#define INVL_F  26000    // per-row 1/L (128)
#define U0_F    26128    // rank-1 chunk-0 contribution (64)
#define PAIR_SMEM_F 26192
#define PAIR_SMEM_BYTES (PAIR_SMEM_F*4)

// 16 k-steps of m16n8k8 over a K=128 panel
__device__ __forceinline__ void mma_panel(const float* sF, int fstride,
                                          const float* sW, float* acc,
                                          int r0, int qrow, int qcol, int nks)
{
    for (int ks = 0; ks < nks; ks++){
        const int kb = ks*8;
        uint32_t a0 = __float_as_uint(sF[(r0    )*fstride + kb + qcol    ]);
        uint32_t a1 = __float_as_uint(sF[(r0 + 8)*fstride + kb + qcol    ]);
        uint32_t a2 = __float_as_uint(sF[(r0    )*fstride + kb + qcol + 4]);
        uint32_t a3 = __float_as_uint(sF[(r0 + 8)*fstride + kb + qcol + 4]);
        #pragma unroll
        for (int nt = 0; nt < 8; nt++){
            uint32_t b0 = __float_as_uint(sW[(nt*8 + qrow)*132 + kb + qcol    ]);
            uint32_t b1v= __float_as_uint(sW[(nt*8 + qrow)*132 + kb + qcol + 4]);
            mma_tf32(acc + nt*4, a0, a1, a2, a3, b0, b1v);
        }
    }
}

__global__ void __launch_bounds__(256)
pair_mlp_mma(const float* __restrict__ x,
    const float* __restrict__ w1, const float* __restrict__ b1,
    const float* __restrict__ w2, const float* __restrict__ b2,
    const float* __restrict__ w3, const float* __restrict__ b3)
{
    extern __shared__ float sm[];
    float* sF = sm + SF_F;
    float* sW = sm + SW_F;

    const int t    = threadIdx.x;
    const int warp = t >> 5;
    const int lane = t & 31;
    const int qrow = lane >> 2;
    const int qcol = lane & 3;
    const int r0   = warp*16 + qrow;

    const int tile = blockIdx.x;
    const int b    = blockIdx.y;
    const int g    = (tile >= 768) ? 3 : (tile >= 384) ? 2 : (tile >= 128) ? 1 : 0;
    const int rem  = tile - 64*g*(g+1);
    const int i    = 128*g + rem/(g+1);
    const int j0   = 128*(rem % (g+1));

    // stage broadcast rows, biases, per-row invL
    if (t < 128){
        sm[XI_F + t] = x[(i*B_ + b)*D_ + t];
        sm[C1_F + t] = g_cum1[(i+1)*BD + b*D_ + t];
        sm[C2_F + t] = g_cum2[(i+1)*BD + b*D_ + t];
        sm[C3_F + t] = g_cum3[(i+1)*BD + b*D_ + t];
        int j = j0 + t;
        sm[INVL_F + t] = (j <= i) ? 1.0f/(float)(i - j + 1) : 0.0f;
    }
    if (t < 64){ sm[B1_F + t] = b1[t]; sm[B2_F + t] = b2[t]; }
    if (t < 16){ sm[B3_F + t] = b3[t]; }
    __syncthreads();

    // rank-1 chunk-0 contribution in fp32: u0[h] = x_i . w1[h][0:128]
    if (t < 64){
        float a = 0.f;
        #pragma unroll 4
        for (int d = 0; d < 128; d++) a += sm[XI_F + d] * w1[t*SIXD + d];
        sm[U0_F + t] = a;
    }

    float acc[32];
    #pragma unroll
    for (int q = 0; q < 32; q++) acc[q] = 0.f;

    // ---------------- layer 1: 4 staged A-tiles, 5 MMA panels ----------------
    for (int c = 0; c < 4; c++){
        __syncthreads();

        // stage W1 panel: c==0 -> cols 128..255 (curB); c>=1 -> moment cols
        const int wcol = (c == 0) ? 128 : (c + 2)*128;
        for (int idx = t; idx < 64*128; idx += 256){
            int h = idx >> 7, d = idx & 127;
            sW[h*132 + d] = __uint_as_float(f2tf32(w1[h*SIXD + wcol + d]));
        }
        // stage feature tile
        if (c == 0){
            for (int idx = t; idx < 128*128; idx += 256){
                int r = idx >> 7, d = idx & 127;
                int j = j0 + r;
                float v = (j <= i) ? x[(j*B_ + b)*D_ + d] : 0.f;
                sF[r*132 + d] = __uint_as_float(f2tf32(v));
            }
        } else {
            const float* cumg = (c == 1) ? g_cum1 : (c == 2) ? g_cum2 : g_cum3;
            const float* cs   = sm + ((c == 1) ? C1_F : (c == 2) ? C2_F : C3_F);
            for (int idx = t; idx < 128*128; idx += 256){
                int r = idx >> 7, d = idx & 127;
                int j = j0 + r;
                float v = (cs[d] - cumg[j*BD + b*D_ + d]) * sm[INVL_F + r];
                sF[r*132 + d] = __uint_as_float(f2tf32(v));
            }
        }
        __syncthreads();

        mma_panel(sF, 132, sW, acc, r0, qrow, qcol, 16);

        if (c == 0){
            // second pass over SAME x_j tile with folded weights
            // W'[h][d] = w1[h][256+d] * x_i[d]  (curA*curB chunk)
            __syncthreads();
            for (int idx = t; idx < 64*128; idx += 256){
                int h = idx >> 7, d = idx & 127;
                sW[h*132 + d] = __uint_as_float(
                    f2tf32(w1[h*SIXD + 256 + d] * sm[XI_F + d]));
            }
            __syncthreads();
            mma_panel(sF, 132, sW, acc, r0, qrow, qcol, 16);
        }
    }
    __syncthreads();

    // ---------------- layer 1 epilogue: bias + u0 + gelu -> sF (stride 68) ---
    #pragma unroll
    for (int nt = 0; nt < 8; nt++){
        const int col = nt*8 + qcol*2;
        float bb0 = sm[B1_F + col    ] + sm[U0_F + col    ];
        float bb1 = sm[B1_F + col + 1] + sm[U0_F + col + 1];
        float v0 = gelu_f(acc[nt*4+0] + bb0);
        float v1 = gelu_f(acc[nt*4+1] + bb1);
        float v2 = gelu_f(acc[nt*4+2] + bb0);
        float v3 = gelu_f(acc[nt*4+3] + bb1);
        sF[(r0    )*68 + col    ] = __uint_as_float(f2tf32(v0));
        sF[(r0    )*68 + col + 1] = __uint_as_float(f2tf32(v1));
        sF[(r0 + 8)*68 + col    ] = __uint_as_float(f2tf32(v2));
        sF[(r0 + 8)*68 + col + 1] = __uint_as_float(f2tf32(v3));
    }
    for (int idx = t; idx < 64*64; idx += 256){
        int h = idx >> 6, k = idx & 63;
        sW[h*132 + k] = __uint_as_float(f2tf32(w2[h*64 + k]));
    }
    __syncthreads();

    // ---------------- layer 2 (tf32 mma) -------------------------------------
    #pragma unroll
    for (int q = 0; q < 32; q++) acc[q] = 0.f;
    mma_panel(sF, 68, sW, acc, r0, qrow, qcol, 8);
    __syncthreads();

    // ---------------- layer 2 epilogue -> h2 fp32; stage W3 fp32 -------------
    #pragma unroll
    for (int nt = 0; nt < 8; nt++){
        const int col = nt*8 + qcol*2;
        sF[(r0    )*68 + col    ] = gelu_f(acc[nt*4+0] + sm[B2_F + col    ]);
        sF[(r0    )*68 + col + 1] = gelu_f(acc[nt*4+1] + sm[B2_F + col + 1]);
        sF[(r0 + 8)*68 + col    ] = gelu_f(acc[nt*4+2] + sm[B2_F + col    ]);
        sF[(r0 + 8)*68 + col + 1] = gelu_f(acc[nt*4+3] + sm[B2_F + col + 1]);
    }
    for (int idx = t; idx < 16*64; idx += 256){
        int o = idx >> 6, k = idx & 63;
        sW[o*68 + k] = w3[o*64 + k];
    }
    __syncthreads();

    // ---------------- layer 3 in fp32 (tiny GEMM) + scatter ------------------
    {
        const int r  = t >> 1;               // 0..127
        const int o0 = (t & 1)*8;
        float a3[8];
        #pragma unroll
        for (int q = 0; q < 8; q++) a3[q] = 0.f;
        #pragma unroll
        for (int k4 = 0; k4 < 16; k4++){
            float4 h4 = *reinterpret_cast<const float4*>(&sF[r*68 + k4*4]);
            #pragma unroll
            for (int q = 0; q < 8; q++){
                float4 w4 = *reinterpret_cast<const float4*>(&sW[(o0+q)*68 + k4*4]);
                a3[q] += h4.x*w4.x + h4.y*w4.y + h4.z*w4.z + h4.w*w4.w;
            }
        }
        const int j = j0 + r;
        if (j <= i){
            #pragma unroll
            for (int q = 0; q < 8; q++)
                g_S0[((b*O_ + o0 + q)*N_ + i)*N_ + j] = a3[q] + sm[B3_F + o0 + q];
        }
    }
}

// ---------------- conv1 (16->48, pad=2) + gelu: 2x2 px, 12-ch groups --------
// grid (17,17, B*4), block (16,16). z = b*4 + cg.
#define C1_SIN_F   19584     // 16 ch x 34 rows x 36 stride
#define C1_SWT_F   (C1_SIN_F)        // then 144 x 12
#define C1_SMEM_F  (19584 + 1728 + 12)
#define C1_SMEM_BYTES (C1_SMEM_F*4)

__global__ void __launch_bounds__(256)
conv1_kernel(const float* __restrict__ cw1, const float* __restrict__ cb1){
    extern __shared__ float smv[];
    float* sIn   = smv;                  // [o][py][px] stride 36, py<34
    float* sWt   = smv + C1_SWT_F;       // [(o*9+kk)*12 + cl]
    float* sBias = sWt + 1728;           // 12
    const int bz = blockIdx.z;
    const int b  = bz >> 2;
    const int cg = bz & 3;               // channel group: out ch cg*12..+11
    const int y0 = blockIdx.y*32, x0 = blockIdx.x*32;
    const int tx = threadIdx.x, ty = threadIdx.y;
    const int t  = ty*16 + tx;

    for (int idx = t; idx < 12*144; idx += 256){
        int cl = idx/144, rem = idx%144;               // rem = o*9+kk
        sWt[rem*12 + cl] = cw1[(cg*12 + cl)*144 + rem];
    }
    if (t < 12) sBias[t] = cb1[cg*12 + t];
    for (int idx = t; idx < 16*34*34; idx += 256){
        int o = idx/1156, p = idx%1156;
        int py = p/34, px = p%34;
        int yy = y0 - 2 + py, xx = x0 - 2 + px;
        float v = 0.f;
        if (yy >= 0 && yy < N_ && xx >= 0 && xx < N_)
            v = g_S0[((b*O_ + o)*N_ + yy)*N_ + xx];
        sIn[o*(34*36) + py*36 + px] = v;
    }
    __syncthreads();

    float acc[4][12];
    #pragma unroll
    for (int p = 0; p < 4; p++)
        #pragma unroll
        for (int cl = 0; cl < 12; cl++) acc[p][cl] = sBias[cl];

    for (int o = 0; o < 16; o++){
        #pragma unroll
        for (int ky = 0; ky < 3; ky++)
            #pragma unroll
            for (int kx = 0; kx < 3; kx++){
                const int base = o*(34*36) + (2*ty + ky)*36 + 2*tx + kx;
                float v00 = sIn[base],      v01 = sIn[base + 1];
                float v10 = sIn[base + 36], v11 = sIn[base + 37];
                const float4* wp = reinterpret_cast<const float4*>(&sWt[(o*9 + ky*3 + kx)*12]);
                #pragma unroll
                for (int c4 = 0; c4 < 3; c4++){
                    float4 w4 = wp[c4];
                    acc[0][c4*4+0] += v00*w4.x; acc[0][c4*4+1] += v00*w4.y;
                    acc[0][c4*4+2] += v00*w4.z; acc[0][c4*4+3] += v00*w4.w;
                    acc[1][c4*4+0] += v01*w4.x; acc[1][c4*4+1] += v01*w4.y;
                    acc[1][c4*4+2] += v01*w4.z; acc[1][c4*4+3] += v01*w4.w;
                    acc[2][c4*4+0] += v10*w4.x; acc[2][c4*4+1] += v10*w4.y;
                    acc[2][c4*4+2] += v10*w4.z; acc[2][c4*4+3] += v10*w4.w;
                    acc[3][c4*4+0] += v11*w4.x; acc[3][c4*4+1] += v11*w4.y;
                    acc[3][c4*4+2] += v11*w4.z; acc[3][c4*4+3] += v11*w4.w;
                }
            }
    }

    #pragma unroll
    for (int p = 0; p < 4; p++){
        const int y = y0 + 2*ty + (p >> 1);
        const int x = x0 + 2*tx + (p & 1);
        if (y < NP_ && x < NP_){
            #pragma unroll
            for (int cl = 0; cl < 12; cl++)
                g_H1[((b*CH_ + cg*12 + cl)*NP_ + y)*NP_ + x] = gelu_f(acc[p][cl]);
        }
    }
}

// ------- conv2 (48->16, valid) + bias + |i-j| scale + permute: 2x2 px -------
// grid (16,16,B), block (16,16). 3 input-channel passes of 16.
#define C2_SIN_F   19584     // 16 ch x 34 x 36
#define C2_SMEM_F  (19584 + 2304 + 16)
#define C2_SMEM_BYTES (C2_SMEM_F*4)

__global__ void __launch_bounds__(256)
conv2_kernel(const float* __restrict__ cw2, const float* __restrict__ cb2,
             float* __restrict__ out){
    extern __shared__ float smv[];
    float* sIn   = smv;                  // [ci][py][px] stride 36, py<34
    float* sWt   = smv + C2_SIN_F;       // [(ci*9+kk)*16 + o]
    float* sBias = sWt + 2304;           // 16
    const int b  = blockIdx.z;
    const int y0 = blockIdx.y*32, x0 = blockIdx.x*32;
    const int tx = threadIdx.x, ty = threadIdx.y;
    const int t  = ty*16 + tx;

    if (t < 16) sBias[t] = cb2[t];
    __syncthreads();

    float acc[4][16];
    #pragma unroll
    for (int p = 0; p < 4; p++)
        #pragma unroll
        for (int o = 0; o < 16; o++) acc[p][o] = sBias[o];

    for (int pass = 0; pass < 3; pass++){
        __syncthreads();
        // stage 16 input channels [16*pass .. ) : rows y0..y0+33 all in-bounds
        for (int idx = t; idx < 16*34*34; idx += 256){
            int ci = idx/1156, p = idx%1156;
            int py = p/34, px = p%34;
            sIn[ci*(34*36) + py*36 + px] =
                g_H1[((b*CH_ + pass*16 + ci)*NP_ + y0 + py)*NP_ + x0 + px];
        }
        for (int idx = t; idx < 16*144; idx += 256){
            int o = idx/144, rem = idx%144;            // rem = ci*9+kk
            sWt[rem*16 + o] = cw2[o*432 + pass*144 + rem];
        }
        __syncthreads();

        for (int ci = 0; ci < 16; ci++){
            #pragma unroll
            for (int ky = 0; ky < 3; ky++)
                #pragma unroll
                for (int kx = 0; kx < 3; kx++){
                    const int base = ci*(34*36) + (2*ty + ky)*36 + 2*tx + kx;
                    float v00 = sIn[base],      v01 = sIn[base + 1];
                    float v10 = sIn[base + 36], v11 = sIn[base + 37];
                    const float4* wp = reinterpret_cast<const float4*>(&sWt[(ci*9 + ky*3 + kx)*16]);
                    #pragma unroll
                    for (int o4 = 0; o4 < 4; o4++){
                        float4 w4 = wp[o4];
                        acc[0][o4*4+0] += v00*w4.x; acc[0][o4*4+1] += v00*w4.y;
                        acc[0][o4*4+2] += v00*w4.z; acc[0][o4*4+3] += v00*w4.w;
                        acc[1][o4*4+0] += v01*w4.x; acc[1][o4*4+1] += v01*w4.y;
                        acc[1][o4*4+2] += v01*w4.z; acc[1][o4*4+3] += v01*w4.w;
                        acc[2][o4*4+0] += v10*w4.x; acc[2][o4*4+1] += v10*w4.y;
                        acc[2][o4*4+2] += v10*w4.z; acc[2][o4*4+3] += v10*w4.w;
                        acc[3][o4*4+0] += v11*w4.x; acc[3][o4*4+1] += v11*w4.y;
                        acc[3][o4*4+2] += v11*w4.z; acc[3][o4*4+3] += v11*w4.w;
                    }
                }
        }
    }

    #pragma unroll
    for (int p = 0; p < 4; p++){
        const int y = y0 + 2*ty + (p >> 1);
        const int x = x0 + 2*tx + (p & 1);
        int diff = y - x; if (diff < 0) diff = -diff; if (diff < 1) diff = 1;
        const float len = (float)diff;
        float4* op = reinterpret_cast<float4*>(&out[((y*N_ + x)*B_ + b)*O_]);
        #pragma unroll
        for (int o4 = 0; o4 < 4; o4++)
            op[o4] = make_float4(len*acc[p][o4*4+0], len*acc[p][o4*4+1],
                                 len*acc[p][o4*4+2], len*acc[p][o4*4+3]);
    }
}

// ---------------- skip MLP ---------------------------------------------------
__global__ void skip_kernel(const float* __restrict__ x,
    const float* __restrict__ sw1, const float* __restrict__ sb1,
    const float* __restrict__ sw2, const float* __restrict__ sb2,
    const float* __restrict__ sw3, const float* __restrict__ sb3,
    float* __restrict__ out){
    __shared__ float sFeat[384];
    __shared__ float sH1[64];
    __shared__ float sH2[64];
    const int i = blockIdx.x, b = blockIdx.y;
    const int t = threadIdx.x;
    {
        float xa = x[(i*B_ + b)*D_ + t];
        float xb = x[((i+1)*B_ + b)*D_ + t];
        sFeat[t] = xa; sFeat[128 + t] = xb; sFeat[256 + t] = xa*xb;
    }
    __syncthreads();
    if (t < 64){
        float a = sb1[t];
        #pragma unroll 4
        for (int k = 0; k < 384; k++) a += sFeat[k]*sw1[t*384 + k];
        sH1[t] = gelu_f(a);
    }
    __syncthreads();
    if (t < 64){
        float a = sb2[t];
        #pragma unroll 4
        for (int k = 0; k < 64; k++) a += sH1[k]*sw2[t*64 + k];
        sH2[t] = gelu_f(a);
    }
    __syncthreads();
    if (t < 16){
        float a = sb3[t];
        #pragma unroll 4
        for (int k = 0; k < 64; k++) a += sH2[k]*sw3[t*64 + k];
        out[(i*B_ + b)*O_ + t] = a;
    }
}

// ---------------------------------------------------------------------------
extern "C" void kernel_launch(void* const* d_in, const int* in_sizes, int n_in,
                              void* d_out, int out_size){
    const float* x   = (const float*)d_in[0];
    const float* w1  = (const float*)d_in[1];
    const float* b1  = (const float*)d_in[2];
    const float* w2  = (const float*)d_in[3];
    const float* b2  = (const float*)d_in[4];
    const float* w3  = (const float*)d_in[5];
    const float* b3  = (const float*)d_in[6];
    const float* sw1 = (const float*)d_in[7];
    const float* sb1 = (const float*)d_in[8];
    const float* sw2 = (const float*)d_in[9];
    const float* sb2 = (const float*)d_in[10];
    const float* sw3 = (const float*)d_in[11];
    const float* sb3 = (const float*)d_in[12];
    const float* cw1 = (const float*)d_in[13];
    const float* cb1 = (const float*)d_in[14];
    const float* cw2 = (const float*)d_in[15];
    const float* cb2 = (const float*)d_in[16];
    float* out = (float*)d_out;

    cudaFuncSetAttribute(pair_mlp_mma, cudaFuncAttributeMaxDynamicSharedMemorySize, PAIR_SMEM_BYTES);
    cudaFuncSetAttribute(conv1_kernel, cudaFuncAttributeMaxDynamicSharedMemorySize, C1_SMEM_BYTES);
    cudaFuncSetAttribute(conv2_kernel, cudaFuncAttributeMaxDynamicSharedMemorySize, C2_SMEM_BYTES);

    cumsum_kernel<<<1, 256>>>(x);
    zero_S0<<<2048, 256>>>();

    pair_mlp_mma<<<dim3(1280, 2), 256, PAIR_SMEM_BYTES>>>(x, w1, b1, w2, b2, w3, b3);

    dim3 blk(16, 16);
    conv1_kernel<<<dim3(17, 17, B_*4), blk, C1_SMEM_BYTES>>>(cw1, cb1);
    conv2_kernel<<<dim3(16, 16, B_), blk, C2_SMEM_BYTES>>>(cw2, cb2, out);

    skip_kernel<<<dim3(N_-1, 2), 128>>>(x, sw1, sb1, sw2, sb2, sw3, sb3,
                                        out + (size_t)N_*N_*B_*O_);
}

// round 9
// speedup vs baseline: 1.9133x; 1.1802x over previous
#include <cuda_runtime.h>
#include <math.h>
#include <stdint.h>

#define N_   512
#define B_   2
#define D_   128
#define O_   16
#define H_   64
#define CH_  48
#define NP_  514
#define SIXD 768
#define BD   (B_*D_)        // 256

// ---------------- scratch ----------------------------------------------------
__device__ float g_cum1[(N_+1)*BD];
__device__ float g_cum2[(N_+1)*BD];
__device__ float g_cum3[(N_+1)*BD];
__device__ float g_S0[B_*O_*N_*N_];      // [b][o][i][j]
__device__ float g_H1[B_*CH_*NP_*NP_];   // [b][c][y][x]
__device__ float g_u0[B_*N_*H_];         // W_curA . x[n]
__device__ float g_v [B_*N_*H_];         // W_curB . x[n]
__device__ float g_U [B_*(N_+1)*H_];     // sum_k W_mk . ck[n]

__device__ __forceinline__ float gelu_f(float v){
    return 0.5f * v * (1.0f + erff(v * 0.70710678118654752f));
}
__device__ __forceinline__ uint32_t f2tf32(float v){
    uint32_t r;
    asm("cvt.rna.tf32.f32 %0, %1;" : "=r"(r) : "f"(v));
    return r;
}
__device__ __forceinline__ void mma_tf32(float* c,
    uint32_t a0, uint32_t a1, uint32_t a2, uint32_t a3, uint32_t b0, uint32_t b1)
{
    asm volatile(
        "mma.sync.aligned.m16n8k8.row.col.f32.tf32.tf32.f32 "
        "{%0,%1,%2,%3}, {%4,%5,%6,%7}, {%8,%9}, {%0,%1,%2,%3};"
        : "+f"(c[0]), "+f"(c[1]), "+f"(c[2]), "+f"(c[3])
        : "r"(a0), "r"(a1), "r"(a2), "r"(a3), "r"(b0), "r"(b1));
}

// ---------------- prefix sums ------------------------------------------------
__global__ void cumsum_kernel(const float* __restrict__ x){
    int t = threadIdx.x;
    float s1 = 0.f, s2 = 0.f, s3 = 0.f;
    g_cum1[t] = 0.f; g_cum2[t] = 0.f; g_cum3[t] = 0.f;
    for (int n = 1; n <= N_; n++){
        float v = x[(n-1)*BD + t];
        s1 += v; s2 += v*v; s3 += v*v*v;
        int idx = n*BD + t;
        g_cum1[idx] = s1; g_cum2[idx] = s2; g_cum3[idx] = s3;
    }
}

__global__ void zero_S0(){
    int i = blockIdx.x*blockDim.x + threadIdx.x;
    int stride = gridDim.x*blockDim.x;
    float4* p = reinterpret_cast<float4*>(g_S0);
    const int n4 = (B_*O_*N_*N_)/4;
    for (; i < n4; i += stride) p[i] = make_float4(0.f,0.f,0.f,0.f);
}

// ------- precompute u0, v, U (fp32 exact): grid (9, B), block 256 -----------
__global__ void __launch_bounds__(256)
precompute_kernel(const float* __restrict__ x, const float* __restrict__ w1){
    extern __shared__ float ps[];
    float* sX = ps;            // 64 x 129
    float* sWt = ps + 8256;    // 64 x 129
    const int n0 = blockIdx.x*64;
    const int b  = blockIdx.y;
    const int t  = threadIdx.x;
    const int tr = t >> 4, tc = t & 15;

    float accA[16], accB[16], accU[16];
    #pragma unroll
    for (int q = 0; q < 16; q++){ accA[q]=0.f; accB[q]=0.f; accU[q]=0.f; }

    for (int cc = 0; cc < 5; cc++){
        __syncthreads();
        const int col0 = (cc == 0) ? 0 : (cc == 1) ? 128 : (cc + 1)*128;
        for (int idx = t; idx < 64*128; idx += 256){
            int h = idx >> 7, d = idx & 127;
            sWt[h*129 + d] = w1[h*SIXD + col0 + d];
        }
        for (int idx = t; idx < 64*128; idx += 256){
            int r = idx >> 7, d = idx & 127;
            int n = n0 + r;
            float v = 0.f;
            if (cc < 2){
                if (n < N_) v = x[(n*B_ + b)*D_ + d];
            } else {
                const float* src = (cc == 2) ? g_cum1 : (cc == 3) ? g_cum2 : g_cum3;
                if (n <= N_) v = src[n*BD + b*D_ + d];
            }
            sX[r*129 + d] = v;
        }
        __syncthreads();

        float* accp = (cc == 0) ? accA : (cc == 1) ? accB : accU;
        #pragma unroll 4
        for (int d = 0; d < 128; d++){
            float fv[4], wv[4];
            #pragma unroll
            for (int a = 0; a < 4; a++) fv[a] = sX[(tr*4 + a)*129 + d];
            #pragma unroll
            for (int q = 0; q < 4; q++) wv[q] = sWt[(tc*4 + q)*129 + d];
            #pragma unroll
            for (int a = 0; a < 4; a++)
                #pragma unroll
                for (int q = 0; q < 4; q++)
                    accp[a*4+q] += fv[a]*wv[q];
        }
    }

    #pragma unroll
    for (int a = 0; a < 4; a++){
        int n = n0 + tr*4 + a;
        #pragma unroll
        for (int q = 0; q < 4; q++){
            int h = tc*4 + q;
            if (n < N_){
                g_u0[(b*N_ + n)*H_ + h] = accA[a*4+q];
                g_v [(b*N_ + n)*H_ + h] = accB[a*4+q];
            }
            if (n <= N_)
                g_U[(b*(N_+1) + n)*H_ + h] = accU[a*4+q];
        }
    }
}

// ---------------- pair MLP: 1 tf32 panel + fp32 epilogue ---------------------
#define SF_F    0        // 128 x 132
#define SW_F    16896    // 64 x 132
#define XI_F    25344
#define INVL_F  25472
#define PRE_F   25600    // b1 + u0[i]  (64)
#define UI1_F   25664    // U[i+1]      (64)
#define B2_F    25728
#define B3_F    25792
#define PAIR_SMEM_F 25808
#define PAIR_SMEM_BYTES (PAIR_SMEM_F*4)

__device__ __forceinline__ void mma_panel(const float* sF, int fstride,
                                          const float* sW, float* acc,
                                          int r0, int qrow, int qcol, int nks)
{
    #pragma unroll
    for (int ks = 0; ks < 16; ks++){
        if (ks >= nks) break;
        const int kb = ks*8;
        uint32_t a0 = __float_as_uint(sF[(r0    )*fstride + kb + qcol    ]);
        uint32_t a1 = __float_as_uint(sF[(r0 + 8)*fstride + kb + qcol    ]);
        uint32_t a2 = __float_as_uint(sF[(r0    )*fstride + kb + qcol + 4]);
        uint32_t a3 = __float_as_uint(sF[(r0 + 8)*fstride + kb + qcol + 4]);
        #pragma unroll
        for (int nt = 0; nt < 8; nt++){
            uint32_t b0 = __float_as_uint(sW[(nt*8 + qrow)*132 + kb + qcol    ]);
            uint32_t b1v= __float_as_uint(sW[(nt*8 + qrow)*132 + kb + qcol + 4]);
            mma_tf32(acc + nt*4, a0, a1, a2, a3, b0, b1v);
        }
    }
}

__global__ void __launch_bounds__(256)
pair_mlp_mma(const float* __restrict__ x,
    const float* __restrict__ w1, const float* __restrict__ b1,
    const float* __restrict__ w2, const float* __restrict__ b2,
    const float* __restrict__ w3, const float* __restrict__ b3)
{
    extern __shared__ float sm[];
    float* sF = sm + SF_F;
    float* sW = sm + SW_F;

    const int t    = threadIdx.x;
    const int warp = t >> 5;
    const int lane = t & 31;
    const int qrow = lane >> 2;
    const int qcol = lane & 3;
    const int r0   = warp*16 + qrow;

    const int tile = blockIdx.x;
    const int b    = blockIdx.y;
    const int g    = (tile >= 768) ? 3 : (tile >= 384) ? 2 : (tile >= 128) ? 1 : 0;
    const int rem  = tile - 64*g*(g+1);
    const int i    = 128*g + rem/(g+1);
    const int j0   = 128*(rem % (g+1));

    if (t < 128){
        sm[XI_F + t] = x[(i*B_ + b)*D_ + t];
        int j = j0 + t;
        sm[INVL_F + t] = (j <= i) ? 1.0f/(float)(i - j + 1) : 0.0f;
    }
    if (t < 64){
        sm[PRE_F + t] = b1[t] + g_u0[(b*N_ + i)*H_ + t];
        sm[UI1_F + t] = g_U[(b*(N_+1) + i + 1)*H_ + t];
        sm[B2_F  + t] = b2[t];
    }
    if (t < 16) sm[B3_F + t] = b3[t];
    __syncthreads();

    // stage x_j tile (tf32) + folded weights Wf = W_AB .* x_i (tf32)
    for (int idx = t; idx < 128*128; idx += 256){
        int r = idx >> 7, d = idx & 127;
        sF[r*132 + d] = __uint_as_float(f2tf32(x[((j0 + r)*B_ + b)*D_ + d]));
    }
    for (int idx = t; idx < 64*128; idx += 256){
        int h = idx >> 7, d = idx & 127;
        sW[h*132 + d] = __uint_as_float(f2tf32(w1[h*SIXD + 256 + d] * sm[XI_F + d]));
    }
    __syncthreads();

    float acc[32];
    #pragma unroll
    for (int q = 0; q < 32; q++) acc[q] = 0.f;
    mma_panel(sF, 132, sW, acc, r0, qrow, qcol, 16);
    __syncthreads();

    // ---- layer-1 epilogue: + pre + v[j] + invL*(U[i+1]-U[j]), gelu -> tf32 --
    {
        const int jA = j0 + r0, jB = j0 + r0 + 8;
        const float ilA = sm[INVL_F + r0], ilB = sm[INVL_F + r0 + 8];
        const float* vA = &g_v[(b*N_ + jA)*H_];
        const float* vB = &g_v[(b*N_ + jB)*H_];
        const float* uA = &g_U[(b*(N_+1) + jA)*H_];
        const float* uB = &g_U[(b*(N_+1) + jB)*H_];
        #pragma unroll
        for (int nt = 0; nt < 8; nt++){
            const int col = nt*8 + qcol*2;
            float pre0 = sm[PRE_F + col], pre1 = sm[PRE_F + col + 1];
            float ui0  = sm[UI1_F + col], ui1  = sm[UI1_F + col + 1];
            float2 vv, uu;
            vv = *reinterpret_cast<const float2*>(vA + col);
            uu = *reinterpret_cast<const float2*>(uA + col);
            sF[(r0    )*68 + col    ] = __uint_as_float(f2tf32(gelu_f(acc[nt*4+0] + pre0 + vv.x + ilA*(ui0 - uu.x))));
            sF[(r0    )*68 + col + 1] = __uint_as_float(f2tf32(gelu_f(acc[nt*4+1] + pre1 + vv.y + ilA*(ui1 - uu.y))));
            vv = *reinterpret_cast<const float2*>(vB + col);
            uu = *reinterpret_cast<const float2*>(uB + col);
            sF[(r0 + 8)*68 + col    ] = __uint_as_float(f2tf32(gelu_f(acc[nt*4+2] + pre0 + vv.x + ilB*(ui0 - uu.x))));
            sF[(r0 + 8)*68 + col + 1] = __uint_as_float(f2tf32(gelu_f(acc[nt*4+3] + pre1 + vv.y + ilB*(ui1 - uu.y))));
        }
    }
    // stage W2 (tf32, stride 132) — sW free after panel sync
    for (int idx = t; idx < 64*64; idx += 256){
        int h = idx >> 6, k = idx & 63;
        sW[h*132 + k] = __uint_as_float(f2tf32(w2[h*64 + k]));
    }
    __syncthreads();

    // ---- layer 2 -------------------------------------------------------------
    #pragma unroll
    for (int q = 0; q < 32; q++) acc[q] = 0.f;
    mma_panel(sF, 68, sW, acc, r0, qrow, qcol, 8);
    __syncthreads();

    // ---- layer-2 epilogue (fp32 h2) + stage W3 fp32 --------------------------
    #pragma unroll
    for (int nt = 0; nt < 8; nt++){
        const int col = nt*8 + qcol*2;
        sF[(r0    )*68 + col    ] = gelu_f(acc[nt*4+0] + sm[B2_F + col    ]);
        sF[(r0    )*68 + col + 1] = gelu_f(acc[nt*4+1] + sm[B2_F + col + 1]);
        sF[(r0 + 8)*68 + col    ] = gelu_f(acc[nt*4+2] + sm[B2_F + col    ]);
        sF[(r0 + 8)*68 + col + 1] = gelu_f(acc[nt*4+3] + sm[B2_F + col + 1]);
    }
    for (int idx = t; idx < 16*64; idx += 256){
        int o = idx >> 6, k = idx & 63;
        sW[o*68 + k] = w3[o*64 + k];
    }
    __syncthreads();

    // ---- layer 3 fp32 + scatter ----------------------------------------------
    {
        const int r  = t >> 1;
        const int o0 = (t & 1)*8;
        float a3[8];
        #pragma unroll
        for (int q = 0; q < 8; q++) a3[q] = 0.f;
        #pragma unroll
        for (int k4 = 0; k4 < 16; k4++){
            float4 h4 = *reinterpret_cast<const float4*>(&sF[r*68 + k4*4]);
            #pragma unroll
            for (int q = 0; q < 8; q++){
                float4 w4 = *reinterpret_cast<const float4*>(&sW[(o0+q)*68 + k4*4]);
                a3[q] += h4.x*w4.x + h4.y*w4.y + h4.z*w4.z + h4.w*w4.w;
            }
        }
        const int j = j0 + r;
        if (j <= i){
            #pragma unroll
            for (int q = 0; q < 8; q++)
                g_S0[((b*O_ + o0 + q)*N_ + i)*N_ + j] = a3[q] + sm[B3_F + o0 + q];
        }
    }
}

// ---------------- conv1 (16->48, pad=2) + gelu ------------------------------
#define C1_SMEM_F  (19584 + 1728 + 12)
#define C1_SMEM_BYTES (C1_SMEM_F*4)

__global__ void __launch_bounds__(256)
conv1_kernel(const float* __restrict__ cw1, const float* __restrict__ cb1){
    extern __shared__ float smv[];
    float* sIn   = smv;                  // [o][py][px] stride 36, 34 rows
    float* sWt   = smv + 19584;          // [(o*9+kk)*12 + cl]
    float* sBias = sWt + 1728;           // 12
    const int bz = blockIdx.z;
    const int b  = bz >> 2;
    const int cg = bz & 3;
    const int y0 = blockIdx.y*32, x0 = blockIdx.x*32;
    const int tx = threadIdx.x, ty = threadIdx.y;
    const int t  = ty*16 + tx;
    const int py = 2*ty, px = 2*tx;

    // triangular skip: whole 36x36 input patch is zero
    if (x0 >= y0 + 64){
        float gv[12];
        #pragma unroll
        for (int cl = 0; cl < 12; cl++) gv[cl] = gelu_f(cb1[cg*12 + cl]);
        #pragma unroll
        for (int p = 0; p < 4; p++){
            const int y = y0 + py + (p >> 1);
            const int x = x0 + px + (p & 1);
            if (y < NP_ && x < NP_){
                #pragma unroll
                for (int cl = 0; cl < 12; cl++)
                    g_H1[((b*CH_ + cg*12 + cl)*NP_ + y)*NP_ + x] = gv[cl];
            }
        }
        return;
    }

    for (int idx = t; idx < 12*144; idx += 256){
        int cl = idx/144, rem = idx%144;
        sWt[rem*12 + cl] = cw1[(cg*12 + cl)*144 + rem];
    }
    if (t < 12) sBias[t] = cb1[cg*12 + t];
    for (int idx = t; idx < 16*34*34; idx += 256){
        int o = idx/1156, p = idx%1156;
        int iy = p/34, ix = p%34;
        int yy = y0 - 2 + iy, xx = x0 - 2 + ix;
        float v = 0.f;
        if (yy >= 0 && yy < N_ && xx >= 0 && xx < N_)
            v = g_S0[((b*O_ + o)*N_ + yy)*N_ + xx];
        sIn[o*1224 + iy*36 + ix] = v;
    }
    __syncthreads();

    float acc[4][12];
    #pragma unroll
    for (int p = 0; p < 4; p++)
        #pragma unroll
        for (int cl = 0; cl < 12; cl++) acc[p][cl] = sBias[cl];

    for (int o = 0; o < 16; o++){
        const float* pI = &sIn[o*1224 + py*36 + px];
        const float* pW = &sWt[o*108];
        #pragma unroll
        for (int ky = 0; ky < 3; ky++){
            #pragma unroll
            for (int kx = 0; kx < 3; kx++){
                float v00 = pI[ky*36 + kx],      v01 = pI[ky*36 + kx + 1];
                float v10 = pI[ky*36 + kx + 36], v11 = pI[ky*36 + kx + 37];
                const float4* wp = reinterpret_cast<const float4*>(pW + (ky*3 + kx)*12);
                #pragma unroll
                for (int c4 = 0; c4 < 3; c4++){
                    float4 w4 = wp[c4];
                    acc[0][c4*4+0] += v00*w4.x; acc[0][c4*4+1] += v00*w4.y;
                    acc[0][c4*4+2] += v00*w4.z; acc[0][c4*4+3] += v00*w4.w;
                    acc[1][c4*4+0] += v01*w4.x; acc[1][c4*4+1] += v01*w4.y;
                    acc[1][c4*4+2] += v01*w4.z; acc[1][c4*4+3] += v01*w4.w;
                    acc[2][c4*4+0] += v10*w4.x; acc[2][c4*4+1] += v10*w4.y;
                    acc[2][c4*4+2] += v10*w4.z; acc[2][c4*4+3] += v10*w4.w;
                    acc[3][c4*4+0] += v11*w4.x; acc[3][c4*4+1] += v11*w4.y;
                    acc[3][c4*4+2] += v11*w4.z; acc[3][c4*4+3] += v11*w4.w;
                }
            }
        }
    }

    #pragma unroll
    for (int p = 0; p < 4; p++){
        const int y = y0 + py + (p >> 1);
        const int x = x0 + px + (p & 1);
        if (y < NP_ && x < NP_){
            #pragma unroll
            for (int cl = 0; cl < 12; cl++)
                g_H1[((b*CH_ + cg*12 + cl)*NP_ + y)*NP_ + x] = gelu_f(acc[p][cl]);
        }
    }
}

// ------- conv2 (48->16, valid) + bias + |i-j| scale + permute ---------------
#define C2_SMEM_F  (19584 + 2304 + 32)
#define C2_SMEM_BYTES (C2_SMEM_F*4)

__global__ void __launch_bounds__(256)
conv2_kernel(const float* __restrict__ cw2, const float* __restrict__ cb2,
             const float* __restrict__ cb1, float* __restrict__ out){
    extern __shared__ float smv[];
    float* sIn   = smv;                  // [ci][py][px] stride 36, 34 rows
    float* sWt   = smv + 19584;          // [(ci*9+kk)*16 + o]
    float* sBias = sWt + 2304;           // 16
    float* sK2   = sBias + 16;           // 16 (const-tile values)
    const int b  = blockIdx.z;
    const int y0 = blockIdx.y*32, x0 = blockIdx.x*32;
    const int tx = threadIdx.x, ty = threadIdx.y;
    const int t  = ty*16 + tx;
    const int py = 2*ty, px = 2*tx;

    // constant-region skip: all inputs are gelu(cb1)
    if (x0 >= y0 + 64){
        if (t < 16){
            float s = cb2[t];
            for (int c = 0; c < CH_; c++){
                float gg = gelu_f(cb1[c]);
                float ws = 0.f;
                #pragma unroll
                for (int kk = 0; kk < 9; kk++) ws += cw2[t*432 + c*9 + kk];
                s += ws*gg;
            }
            sK2[t] = s;
        }
        __syncthreads();
        #pragma unroll
        for (int p = 0; p < 4; p++){
            const int y = y0 + py + (p >> 1);
            const int x = x0 + px + (p & 1);
            const float len = (float)(x - y);   // x > y+4 here
            float4* op = reinterpret_cast<float4*>(&out[((y*N_ + x)*B_ + b)*O_]);
            #pragma unroll
            for (int o4 = 0; o4 < 4; o4++)
                op[o4] = make_float4(len*sK2[o4*4+0], len*sK2[o4*4+1],
                                     len*sK2[o4*4+2], len*sK2[o4*4+3]);
        }
        return;
    }

    if (t < 16) sBias[t] = cb2[t];
    __syncthreads();

    float acc[4][16];
    #pragma unroll
    for (int p = 0; p < 4; p++)
        #pragma unroll
        for (int o = 0; o < 16; o++) acc[p][o] = sBias[o];

    for (int pass = 0; pass < 3; pass++){
        __syncthreads();
        for (int idx = t; idx < 16*34*34; idx += 256){
            int ci = idx/1156, p = idx%1156;
            int iy = p/34, ix = p%34;
            sIn[ci*1224 + iy*36 + ix] =
                g_H1[((b*CH_ + pass*16 + ci)*NP_ + y0 + iy)*NP_ + x0 + ix];
        }
        for (int idx = t; idx < 16*144; idx += 256){
            int o = idx/144, rem = idx%144;
            sWt[rem*16 + o] = cw2[o*432 + pass*144 + rem];
        }
        __syncthreads();

        for (int ci = 0; ci < 16; ci++){
            const float* pI = &sIn[ci*1224 + py*36 + px];
            const float* pW = &sWt[ci*144];
            #pragma unroll
            for (int ky = 0; ky < 3; ky++){
                #pragma unroll
                for (int kx = 0; kx < 3; kx++){
                    float v00 = pI[ky*36 + kx],      v01 = pI[ky*36 + kx + 1];
                    float v10 = pI[ky*36 + kx + 36], v11 = pI[ky*36 + kx + 37];
                    const float4* wp = reinterpret_cast<const float4*>(pW + (ky*3 + kx)*16);
                    #pragma unroll
                    for (int o4 = 0; o4 < 4; o4++){
                        float4 w4 = wp[o4];
                        acc[0][o4*4+0] += v00*w4.x; acc[0][o4*4+1] += v00*w4.y;
                        acc[0][o4*4+2] += v00*w4.z; acc[0][o4*4+3] += v00*w4.w;
                        acc[1][o4*4+0] += v01*w4.x; acc[1][o4*4+1] += v01*w4.y;
                        acc[1][o4*4+2] += v01*w4.z; acc[1][o4*4+3] += v01*w4.w;
                        acc[2][o4*4+0] += v10*w4.x; acc[2][o4*4+1] += v10*w4.y;
                        acc[2][o4*4+2] += v10*w4.z; acc[2][o4*4+3] += v10*w4.w;
                        acc[3][o4*4+0] += v11*w4.x; acc[3][o4*4+1] += v11*w4.y;
                        acc[3][o4*4+2] += v11*w4.z; acc[3][o4*4+3] += v11*w4.w;
                    }
                }
            }
        }
    }

    #pragma unroll
    for (int p = 0; p < 4; p++){
        const int y = y0 + py + (p >> 1);
        const int x = x0 + px + (p & 1);
        int diff = y - x; if (diff < 0) diff = -diff; if (diff < 1) diff = 1;
        const float len = (float)diff;
        float4* op = reinterpret_cast<float4*>(&out[((y*N_ + x)*B_ + b)*O_]);
        #pragma unroll
        for (int o4 = 0; o4 < 4; o4++)
            op[o4] = make_float4(len*acc[p][o4*4+0], len*acc[p][o4*4+1],
                                 len*acc[p][o4*4+2], len*acc[p][o4*4+3]);
    }
}

// ---------------- skip MLP ---------------------------------------------------
__global__ void skip_kernel(const float* __restrict__ x,
    const float* __restrict__ sw1, const float* __restrict__ sb1,
    const float* __restrict__ sw2, const float* __restrict__ sb2,
    const float* __restrict__ sw3, const float* __restrict__ sb3,
    float* __restrict__ out){
    __shared__ float sFeat[384];
    __shared__ float sH1[64];
    __shared__ float sH2[64];
    const int i = blockIdx.x, b = blockIdx.y;
    const int t = threadIdx.x;
    {
        float xa = x[(i*B_ + b)*D_ + t];
        float xb = x[((i+1)*B_ + b)*D_ + t];
        sFeat[t] = xa; sFeat[128 + t] = xb; sFeat[256 + t] = xa*xb;
    }
    __syncthreads();
    if (t < 64){
        float a = sb1[t];
        #pragma unroll 4
        for (int k = 0; k < 384; k++) a += sFeat[k]*sw1[t*384 + k];
        sH1[t] = gelu_f(a);
    }
    __syncthreads();
    if (t < 64){
        float a = sb2[t];
        #pragma unroll 4
        for (int k = 0; k < 64; k++) a += sH1[k]*sw2[t*64 + k];
        sH2[t] = gelu_f(a);
    }
    __syncthreads();
    if (t < 16){
        float a = sb3[t];
        #pragma unroll 4
        for (int k = 0; k < 64; k++) a += sH2[k]*sw3[t*64 + k];
        out[(i*B_ + b)*O_ + t] = a;
    }
}

// ---------------------------------------------------------------------------
extern "C" void kernel_launch(void* const* d_in, const int* in_sizes, int n_in,
                              void* d_out, int out_size){
    const float* x   = (const float*)d_in[0];
    const float* w1  = (const float*)d_in[1];
    const float* b1  = (const float*)d_in[2];
    const float* w2  = (const float*)d_in[3];
    const float* b2  = (const float*)d_in[4];
    const float* w3  = (const float*)d_in[5];
    const float* b3  = (const float*)d_in[6];
    const float* sw1 = (const float*)d_in[7];
    const float* sb1 = (const float*)d_in[8];
    const float* sw2 = (const float*)d_in[9];
    const float* sb2 = (const float*)d_in[10];
    const float* sw3 = (const float*)d_in[11];
    const float* sb3 = (const float*)d_in[12];
    const float* cw1 = (const float*)d_in[13];
    const float* cb1 = (const float*)d_in[14];
    const float* cw2 = (const float*)d_in[15];
    const float* cb2 = (const float*)d_in[16];
    float* out = (float*)d_out;

    const int pre_smem = 16512*4;
    cudaFuncSetAttribute(precompute_kernel, cudaFuncAttributeMaxDynamicSharedMemorySize, pre_smem);
    cudaFuncSetAttribute(pair_mlp_mma, cudaFuncAttributeMaxDynamicSharedMemorySize, PAIR_SMEM_BYTES);
    cudaFuncSetAttribute(conv1_kernel, cudaFuncAttributeMaxDynamicSharedMemorySize, C1_SMEM_BYTES);
    cudaFuncSetAttribute(conv2_kernel, cudaFuncAttributeMaxDynamicSharedMemorySize, C2_SMEM_BYTES);

    cumsum_kernel<<<1, 256>>>(x);
    zero_S0<<<2048, 256>>>();
    precompute_kernel<<<dim3(9, B_), 256, pre_smem>>>(x, w1);

    pair_mlp_mma<<<dim3(1280, 2), 256, PAIR_SMEM_BYTES>>>(x, w1, b1, w2, b2, w3, b3);

    dim3 blk(16, 16);
    conv1_kernel<<<dim3(17, 17, B_*4), blk, C1_SMEM_BYTES>>>(cw1, cb1);
    conv2_kernel<<<dim3(16, 16, B_), blk, C2_SMEM_BYTES>>>(cw2, cb2, cb1, out);

    skip_kernel<<<dim3(N_-1, 2), 128>>>(x, sw1, sb1, sw2, sb2, sw3, sb3,
                                        out + (size_t)N_*N_*B_*O_);
}

// round 10
// speedup vs baseline: 2.5831x; 1.3501x over previous
#include <cuda_runtime.h>
#include <math.h>
#include <stdint.h>

#define N_   512
#define B_   2
#define D_   128
#define O_   16
#define H_   64
#define CH_  48
#define NP_  514
#define SIXD 768
#define BD   (B_*D_)        // 256

// ---------------- scratch ----------------------------------------------------
__device__ float g_cum1[(N_+1)*BD];
__device__ float g_cum2[(N_+1)*BD];
__device__ float g_cum3[(N_+1)*BD];
__device__ float g_S0[B_*O_*N_*N_];      // [b][o][i][j]
__device__ float g_H1[B_*CH_*NP_*NP_];   // [b][c][y][x]
__device__ float g_u0[B_*N_*H_];         // W_curA . x[n]
__device__ float g_v [B_*N_*H_];         // W_curB . x[n]
__device__ float g_U [B_*(N_+1)*H_];     // sum_k W_mk . ck[n]

__device__ __forceinline__ float gelu_f(float v){
    return 0.5f * v * (1.0f + erff(v * 0.70710678118654752f));
}
__device__ __forceinline__ uint32_t f2tf32(float v){
    uint32_t r;
    asm("cvt.rna.tf32.f32 %0, %1;" : "=r"(r) : "f"(v));
    return r;
}
__device__ __forceinline__ void mma_tf32(float* c,
    uint32_t a0, uint32_t a1, uint32_t a2, uint32_t a3, uint32_t b0, uint32_t b1)
{
    asm volatile(
        "mma.sync.aligned.m16n8k8.row.col.f32.tf32.tf32.f32 "
        "{%0,%1,%2,%3}, {%4,%5,%6,%7}, {%8,%9}, {%0,%1,%2,%3};"
        : "+f"(c[0]), "+f"(c[1]), "+f"(c[2]), "+f"(c[3])
        : "r"(a0), "r"(a1), "r"(a2), "r"(a3), "r"(b0), "r"(b1));
}

// ---------------- parallel prefix sums (Hillis-Steele scan) ------------------
__global__ void __launch_bounds__(512)
scan_kernel(const float* __restrict__ x){
    __shared__ float s1[512], s2[512], s3[512];
    const int bd = blockIdx.x;       // (b,d) flattened, 0..255
    const int n  = threadIdx.x;      // 0..511
    float v = x[n*BD + bd];
    float a = v, bb = v*v, c = v*v*v;
    s1[n] = a; s2[n] = bb; s3[n] = c;
    #pragma unroll
    for (int off = 1; off < 512; off <<= 1){
        __syncthreads();
        float ta = 0.f, tb = 0.f, tc = 0.f;
        if (n >= off){ ta = s1[n-off]; tb = s2[n-off]; tc = s3[n-off]; }
        __syncthreads();
        if (n >= off){
            a += ta; bb += tb; c += tc;
            s1[n] = a; s2[n] = bb; s3[n] = c;
        }
    }
    g_cum1[(n+1)*BD + bd] = a;
    g_cum2[(n+1)*BD + bd] = bb;
    g_cum3[(n+1)*BD + bd] = c;
    if (n == 0){ g_cum1[bd] = 0.f; g_cum2[bd] = 0.f; g_cum3[bd] = 0.f; }
}

__global__ void zero_S0(){
    int i = blockIdx.x*blockDim.x + threadIdx.x;
    int stride = gridDim.x*blockDim.x;
    float4* p = reinterpret_cast<float4*>(g_S0);
    const int n4 = (B_*O_*N_*N_)/4;
    for (; i < n4; i += stride) p[i] = make_float4(0.f,0.f,0.f,0.f);
}

// ------- precompute u0, v, U (fp32 exact): grid (9, B), block 256 -----------
__global__ void __launch_bounds__(256)
precompute_kernel(const float* __restrict__ x, const float* __restrict__ w1){
    extern __shared__ float ps[];
    float* sX = ps;            // 64 x 129
    float* sWt = ps + 8256;    // 64 x 129
    const int n0 = blockIdx.x*64;
    const int b  = blockIdx.y;
    const int t  = threadIdx.x;
    const int tr = t >> 4, tc = t & 15;

    float accA[16], accB[16], accU[16];
    #pragma unroll
    for (int q = 0; q < 16; q++){ accA[q]=0.f; accB[q]=0.f; accU[q]=0.f; }

    for (int cc = 0; cc < 5; cc++){
        __syncthreads();
        const int col0 = (cc == 0) ? 0 : (cc == 1) ? 128 : (cc + 1)*128;
        for (int idx = t; idx < 64*128; idx += 256){
            int h = idx >> 7, d = idx & 127;
            sWt[h*129 + d] = w1[h*SIXD + col0 + d];
        }
        for (int idx = t; idx < 64*128; idx += 256){
            int r = idx >> 7, d = idx & 127;
            int n = n0 + r;
            float v = 0.f;
            if (cc < 2){
                if (n < N_) v = x[(n*B_ + b)*D_ + d];
            } else {
                const float* src = (cc == 2) ? g_cum1 : (cc == 3) ? g_cum2 : g_cum3;
                if (n <= N_) v = src[n*BD + b*D_ + d];
            }
            sX[r*129 + d] = v;
        }
        __syncthreads();

        float* accp = (cc == 0) ? accA : (cc == 1) ? accB : accU;
        #pragma unroll 4
        for (int d = 0; d < 128; d++){
            float fv[4], wv[4];
            #pragma unroll
            for (int a = 0; a < 4; a++) fv[a] = sX[(tr*4 + a)*129 + d];
            #pragma unroll
            for (int q = 0; q < 4; q++) wv[q] = sWt[(tc*4 + q)*129 + d];
            #pragma unroll
            for (int a = 0; a < 4; a++)
                #pragma unroll
                for (int q = 0; q < 4; q++)
                    accp[a*4+q] += fv[a]*wv[q];
        }
    }

    #pragma unroll
    for (int a = 0; a < 4; a++){
        int n = n0 + tr*4 + a;
        #pragma unroll
        for (int q = 0; q < 4; q++){
            int h = tc*4 + q;
            if (n < N_){
                g_u0[(b*N_ + n)*H_ + h] = accA[a*4+q];
                g_v [(b*N_ + n)*H_ + h] = accB[a*4+q];
            }
            if (n <= N_)
                g_U[(b*(N_+1) + n)*H_ + h] = accU[a*4+q];
        }
    }
}

// ---------------- pair MLP: 256-row tiles, 32 rows/warp ----------------------
#define SF_F    0        // 256 x 132 (layer1) / 256 x 68 (layer2/3)
#define SW_F    33792    // 64 x 132
#define XI_F    42240
#define INVL_F  42368    // 256
#define PRE_F   42624    // b1 + u0[i]  (64)
#define UI1_F   42688    // U[i+1]      (64)
#define B2_F    42752
#define B3_F    42816
#define PAIR_SMEM_F 42832
#define PAIR_SMEM_BYTES (PAIR_SMEM_F*4)

__global__ void __launch_bounds__(256)
pair_mlp_mma(const float* __restrict__ x,
    const float* __restrict__ w1, const float* __restrict__ b1,
    const float* __restrict__ w2, const float* __restrict__ b2,
    const float* __restrict__ w3, const float* __restrict__ b3)
{
    extern __shared__ float sm[];
    float* sF = sm + SF_F;
    float* sW = sm + SW_F;

    const int t    = threadIdx.x;
    const int warp = t >> 5;
    const int lane = t & 31;
    const int qrow = lane >> 2;
    const int qcol = lane & 3;
    const int r0   = warp*32 + qrow;    // tile0 base row; tile1 = r0+16

    const int tile = blockIdx.x;
    const int b    = blockIdx.y;
    int i, j0;
    if (tile < 256){ i = tile; j0 = 0; }
    else { i = 256 + ((tile - 256) >> 1); j0 = ((tile - 256) & 1) << 8; }

    // stage scalars
    if (t < 128) sm[XI_F + t] = x[(i*B_ + b)*D_ + t];
    for (int r = t; r < 256; r += 256){
        int j = j0 + r;
        sm[INVL_F + r] = (j <= i) ? 1.0f/(float)(i - j + 1) : 0.0f;
    }
    if (t < 64){
        sm[PRE_F + t] = b1[t] + g_u0[(b*N_ + i)*H_ + t];
        sm[UI1_F + t] = g_U[(b*(N_+1) + i + 1)*H_ + t];
        sm[B2_F  + t] = b2[t];
    }
    if (t < 16) sm[B3_F + t] = b3[t];

    // stage x_j tile (256 x 128, tf32) — no dependency on XI
    for (int idx = t; idx < 256*32; idx += 256){
        int r = idx >> 5, d4 = idx & 31;
        float4 v = *reinterpret_cast<const float4*>(&x[((j0 + r)*B_ + b)*D_ + d4*4]);
        float4 o;
        o.x = __uint_as_float(f2tf32(v.x)); o.y = __uint_as_float(f2tf32(v.y));
        o.z = __uint_as_float(f2tf32(v.z)); o.w = __uint_as_float(f2tf32(v.w));
        *reinterpret_cast<float4*>(&sF[r*132 + d4*4]) = o;
    }
    __syncthreads();

    // stage folded weights Wf = W_AB .* x_i (tf32)
    for (int idx = t; idx < 64*32; idx += 256){
        int h = idx >> 5, d4 = idx & 31;
        float4 wv = *reinterpret_cast<const float4*>(&w1[h*SIXD + 256 + d4*4]);
        float4 xi = *reinterpret_cast<const float4*>(&sm[XI_F + d4*4]);
        float4 o;
        o.x = __uint_as_float(f2tf32(wv.x*xi.x)); o.y = __uint_as_float(f2tf32(wv.y*xi.y));
        o.z = __uint_as_float(f2tf32(wv.z*xi.z)); o.w = __uint_as_float(f2tf32(wv.w*xi.w));
        *reinterpret_cast<float4*>(&sW[h*132 + d4*4]) = o;
    }
    __syncthreads();

    float acc[64];
    #pragma unroll
    for (int q = 0; q < 64; q++) acc[q] = 0.f;

    // ---- layer 1 mma: K=128, two m16 row-tiles share B fragments ------------
    {
        const float* pa = sF + r0*132 + qcol;
        const float* pw = sW + qrow*132 + qcol;
        #pragma unroll
        for (int ks = 0; ks < 16; ks++){
            const int kb = ks*8;
            uint32_t a0 = __float_as_uint(pa[kb]);
            uint32_t a1 = __float_as_uint(pa[kb + 8*132]);
            uint32_t a2 = __float_as_uint(pa[kb + 4]);
            uint32_t a3 = __float_as_uint(pa[kb + 8*132 + 4]);
            uint32_t c0 = __float_as_uint(pa[kb + 16*132]);
            uint32_t c1 = __float_as_uint(pa[kb + 24*132]);
            uint32_t c2 = __float_as_uint(pa[kb + 16*132 + 4]);
            uint32_t c3 = __float_as_uint(pa[kb + 24*132 + 4]);
            #pragma unroll
            for (int nt = 0; nt < 8; nt++){
                uint32_t b0 = __float_as_uint(pw[nt*8*132 + kb]);
                uint32_t b1v= __float_as_uint(pw[nt*8*132 + kb + 4]);
                mma_tf32(acc      + nt*4, a0, a1, a2, a3, b0, b1v);
                mma_tf32(acc + 32 + nt*4, c0, c1, c2, c3, b0, b1v);
            }
        }
    }
    __syncthreads();

    // ---- layer-1 epilogue: + pre + v[j] + invL*(U[i+1]-U[j]), gelu -> tf32 --
    #pragma unroll
    for (int rr = 0; rr < 4; rr++){
        const int r  = r0 + rr*8;
        const int jr = j0 + r;
        const float il = sm[INVL_F + r];
        const float* vr = &g_v[(b*N_ + jr)*H_];
        const float* ur = &g_U[(b*(N_+1) + jr)*H_];
        float* dst = sF + r*68;
        const int base = (rr >> 1)*32 + (rr & 1)*2;
        #pragma unroll
        for (int nt = 0; nt < 8; nt++){
            const int col = nt*8 + qcol*2;
            float2 vv = *reinterpret_cast<const float2*>(vr + col);
            float2 uu = *reinterpret_cast<const float2*>(ur + col);
            float p0 = sm[PRE_F + col], p1 = sm[PRE_F + col + 1];
            float u0v = sm[UI1_F + col], u1v = sm[UI1_F + col + 1];
            dst[col    ] = __uint_as_float(f2tf32(gelu_f(acc[base + nt*4    ] + p0 + vv.x + il*(u0v - uu.x))));
            dst[col + 1] = __uint_as_float(f2tf32(gelu_f(acc[base + nt*4 + 1] + p1 + vv.y + il*(u1v - uu.y))));
        }
    }
    // stage W2 (tf32, stride 132)
    for (int idx = t; idx < 64*64; idx += 256){
        int h = idx >> 6, k = idx & 63;
        sW[h*132 + k] = __uint_as_float(f2tf32(w2[h*64 + k]));
    }
    __syncthreads();

    // ---- layer 2 mma: K=64 ---------------------------------------------------
    #pragma unroll
    for (int q = 0; q < 64; q++) acc[q] = 0.f;
    {
        const float* pa = sF + r0*68 + qcol;
        const float* pw = sW + qrow*132 + qcol;
        #pragma unroll
        for (int ks = 0; ks < 8; ks++){
            const int kb = ks*8;
            uint32_t a0 = __float_as_uint(pa[kb]);
            uint32_t a1 = __float_as_uint(pa[kb + 8*68]);
            uint32_t a2 = __float_as_uint(pa[kb + 4]);
            uint32_t a3 = __float_as_uint(pa[kb + 8*68 + 4]);
            uint32_t c0 = __float_as_uint(pa[kb + 16*68]);
            uint32_t c1 = __float_as_uint(pa[kb + 24*68]);
            uint32_t c2 = __float_as_uint(pa[kb + 16*68 + 4]);
            uint32_t c3 = __float_as_uint(pa[kb + 24*68 + 4]);
            #pragma unroll
            for (int nt = 0; nt < 8; nt++){
                uint32_t b0 = __float_as_uint(pw[nt*8*132 + kb]);
                uint32_t b1v= __float_as_uint(pw[nt*8*132 + kb + 4]);
                mma_tf32(acc      + nt*4, a0, a1, a2, a3, b0, b1v);
                mma_tf32(acc + 32 + nt*4, c0, c1, c2, c3, b0, b1v);
            }
        }
    }
    __syncthreads();

    // ---- layer-2 epilogue (fp32 h2 in place) + stage W3 fp32 -----------------
    #pragma unroll
    for (int rr = 0; rr < 4; rr++){
        const int r = r0 + rr*8;
        float* dst = sF + r*68;
        const int base = (rr >> 1)*32 + (rr & 1)*2;
        #pragma unroll
        for (int nt = 0; nt < 8; nt++){
            const int col = nt*8 + qcol*2;
            dst[col    ] = gelu_f(acc[base + nt*4    ] + sm[B2_F + col    ]);
            dst[col + 1] = gelu_f(acc[base + nt*4 + 1] + sm[B2_F + col + 1]);
        }
    }
    for (int idx = t; idx < 16*64; idx += 256){
        int o = idx >> 6, k = idx & 63;
        sW[o*68 + k] = w3[o*64 + k];
    }
    __syncthreads();

    // ---- layer 3 fp32 + scatter ----------------------------------------------
    #pragma unroll
    for (int half = 0; half < 2; half++){
        const int r  = half*128 + (t >> 1);
        const int o0 = (t & 1)*8;
        float a3[8];
        #pragma unroll
        for (int q = 0; q < 8; q++) a3[q] = 0.f;
        #pragma unroll
        for (int k4 = 0; k4 < 16; k4++){
            float4 h4 = *reinterpret_cast<const float4*>(&sF[r*68 + k4*4]);
            #pragma unroll
            for (int q = 0; q < 8; q++){
                float4 w4 = *reinterpret_cast<const float4*>(&sW[(o0+q)*68 + k4*4]);
                a3[q] += h4.x*w4.x + h4.y*w4.y + h4.z*w4.z + h4.w*w4.w;
            }
        }
        const int j = j0 + r;
        if (j <= i){
            #pragma unroll
            for (int q = 0; q < 8; q++)
                g_S0[((b*O_ + o0 + q)*N_ + i)*N_ + j] = a3[q] + sm[B3_F + o0 + q];
        }
    }
}

// ---------------- conv1 (16->48, pad=2) + gelu ------------------------------
#define C1_SMEM_F  (19584 + 1728 + 12)
#define C1_SMEM_BYTES (C1_SMEM_F*4)

__global__ void __launch_bounds__(256)
conv1_kernel(const float* __restrict__ cw1, const float* __restrict__ cb1){
    extern __shared__ float smv[];
    float* sIn   = smv;                  // [o][py][px] stride 36, 34 rows
    float* sWt   = smv + 19584;          // [(o*9+kk)*12 + cl]
    float* sBias = sWt + 1728;           // 12
    const int bz = blockIdx.z;
    const int b  = bz >> 2;
    const int cg = bz & 3;
    const int y0 = blockIdx.y*32, x0 = blockIdx.x*32;
    const int tx = threadIdx.x, ty = threadIdx.y;
    const int t  = ty*16 + tx;
    const int py = 2*ty, px = 2*tx;

    if (x0 >= y0 + 64){
        float gv[12];
        #pragma unroll
        for (int cl = 0; cl < 12; cl++) gv[cl] = gelu_f(cb1[cg*12 + cl]);
        #pragma unroll
        for (int p = 0; p < 4; p++){
            const int y = y0 + py + (p >> 1);
            const int x = x0 + px + (p & 1);
            if (y < NP_ && x < NP_){
                #pragma unroll
                for (int cl = 0; cl < 12; cl++)
                    g_H1[((b*CH_ + cg*12 + cl)*NP_ + y)*NP_ + x] = gv[cl];
            }
        }
        return;
    }

    for (int idx = t; idx < 12*144; idx += 256){
        int cl = idx/144, rem = idx%144;
        sWt[rem*12 + cl] = cw1[(cg*12 + cl)*144 + rem];
    }
    if (t < 12) sBias[t] = cb1[cg*12 + t];
    for (int idx = t; idx < 16*34*34; idx += 256){
        int o = idx/1156, p = idx%1156;
        int iy = p/34, ix = p%34;
        int yy = y0 - 2 + iy, xx = x0 - 2 + ix;
        float v = 0.f;
        if (yy >= 0 && yy < N_ && xx >= 0 && xx < N_)
            v = g_S0[((b*O_ + o)*N_ + yy)*N_ + xx];
        sIn[o*1224 + iy*36 + ix] = v;
    }
    __syncthreads();

    float acc[4][12];
    #pragma unroll
    for (int p = 0; p < 4; p++)
        #pragma unroll
        for (int cl = 0; cl < 12; cl++) acc[p][cl] = sBias[cl];

    for (int o = 0; o < 16; o++){
        const float* pI = &sIn[o*1224 + py*36 + px];
        const float* pW = &sWt[o*108];
        #pragma unroll
        for (int ky = 0; ky < 3; ky++){
            #pragma unroll
            for (int kx = 0; kx < 3; kx++){
                float v00 = pI[ky*36 + kx],      v01 = pI[ky*36 + kx + 1];
                float v10 = pI[ky*36 + kx + 36], v11 = pI[ky*36 + kx + 37];
                const float4* wp = reinterpret_cast<const float4*>(pW + (ky*3 + kx)*12);
                #pragma unroll
                for (int c4 = 0; c4 < 3; c4++){
                    float4 w4 = wp[c4];
                    acc[0][c4*4+0] += v00*w4.x; acc[0][c4*4+1] += v00*w4.y;
                    acc[0][c4*4+2] += v00*w4.z; acc[0][c4*4+3] += v00*w4.w;
                    acc[1][c4*4+0] += v01*w4.x; acc[1][c4*4+1] += v01*w4.y;
                    acc[1][c4*4+2] += v01*w4.z; acc[1][c4*4+3] += v01*w4.w;
                    acc[2][c4*4+0] += v10*w4.x; acc[2][c4*4+1] += v10*w4.y;
                    acc[2][c4*4+2] += v10*w4.z; acc[2][c4*4+3] += v10*w4.w;
                    acc[3][c4*4+0] += v11*w4.x; acc[3][c4*4+1] += v11*w4.y;
                    acc[3][c4*4+2] += v11*w4.z; acc[3][c4*4+3] += v11*w4.w;
                }
            }
        }
    }

    #pragma unroll
    for (int p = 0; p < 4; p++){
        const int y = y0 + py + (p >> 1);
        const int x = x0 + px + (p & 1);
        if (y < NP_ && x < NP_){
            #pragma unroll
            for (int cl = 0; cl < 12; cl++)
                g_H1[((b*CH_ + cg*12 + cl)*NP_ + y)*NP_ + x] = gelu_f(acc[p][cl]);
        }
    }
}

// ------- conv2 (48->16, valid) + bias + |i-j| scale + permute ---------------
#define C2_SMEM_F  (19584 + 2304 + 32)
#define C2_SMEM_BYTES (C2_SMEM_F*4)

__global__ void __launch_bounds__(256)
conv2_kernel(const float* __restrict__ cw2, const float* __restrict__ cb2,
             const float* __restrict__ cb1, float* __restrict__ out){
    extern __shared__ float smv[];
    float* sIn   = smv;
    float* sWt   = smv + 19584;
    float* sBias = sWt + 2304;
    float* sK2   = sBias + 16;
    const int b  = blockIdx.z;
    const int y0 = blockIdx.y*32, x0 = blockIdx.x*32;
    const int tx = threadIdx.x, ty = threadIdx.y;
    const int t  = ty*16 + tx;
    const int py = 2*ty, px = 2*tx;

    if (x0 >= y0 + 64){
        if (t < 16){
            float s = cb2[t];
            for (int c = 0; c < CH_; c++){
                float gg = gelu_f(cb1[c]);
                float ws = 0.f;
                #pragma unroll
                for (int kk = 0; kk < 9; kk++) ws += cw2[t*432 + c*9 + kk];
                s += ws*gg;
            }
            sK2[t] = s;
        }
        __syncthreads();
        #pragma unroll
        for (int p = 0; p < 4; p++){
            const int y = y0 + py + (p >> 1);
            const int x = x0 + px + (p & 1);
            const float len = (float)(x - y);
            float4* op = reinterpret_cast<float4*>(&out[((y*N_ + x)*B_ + b)*O_]);
            #pragma unroll
            for (int o4 = 0; o4 < 4; o4++)
                op[o4] = make_float4(len*sK2[o4*4+0], len*sK2[o4*4+1],
                                     len*sK2[o4*4+2], len*sK2[o4*4+3]);
        }
        return;
    }

    if (t < 16) sBias[t] = cb2[t];
    __syncthreads();

    float acc[4][16];
    #pragma unroll
    for (int p = 0; p < 4; p++)
        #pragma unroll
        for (int o = 0; o < 16; o++) acc[p][o] = sBias[o];

    for (int pass = 0; pass < 3; pass++){
        __syncthreads();
        for (int idx = t; idx < 16*34*34; idx += 256){
            int ci = idx/1156, p = idx%1156;
            int iy = p/34, ix = p%34;
            sIn[ci*1224 + iy*36 + ix] =
                g_H1[((b*CH_ + pass*16 + ci)*NP_ + y0 + iy)*NP_ + x0 + ix];
        }
        for (int idx = t; idx < 16*144; idx += 256){
            int o = idx/144, rem = idx%144;
            sWt[rem*16 + o] = cw2[o*432 + pass*144 + rem];
        }
        __syncthreads();

        for (int ci = 0; ci < 16; ci++){
            const float* pI = &sIn[ci*1224 + py*36 + px];
            const float* pW = &sWt[ci*144];
            #pragma unroll
            for (int ky = 0; ky < 3; ky++){
                #pragma unroll
                for (int kx = 0; kx < 3; kx++){
                    float v00 = pI[ky*36 + kx],      v01 = pI[ky*36 + kx + 1];
                    float v10 = pI[ky*36 + kx + 36], v11 = pI[ky*36 + kx + 37];
                    const float4* wp = reinterpret_cast<const float4*>(pW + (ky*3 + kx)*16);
                    #pragma unroll
                    for (int o4 = 0; o4 < 4; o4++){
                        float4 w4 = wp[o4];
                        acc[0][o4*4+0] += v00*w4.x; acc[0][o4*4+1] += v00*w4.y;
                        acc[0][o4*4+2] += v00*w4.z; acc[0][o4*4+3] += v00*w4.w;
                        acc[1][o4*4+0] += v01*w4.x; acc[1][o4*4+1] += v01*w4.y;
                        acc[1][o4*4+2] += v01*w4.z; acc[1][o4*4+3] += v01*w4.w;
                        acc[2][o4*4+0] += v10*w4.x; acc[2][o4*4+1] += v10*w4.y;
                        acc[2][o4*4+2] += v10*w4.z; acc[2][o4*4+3] += v10*w4.w;
                        acc[3][o4*4+0] += v11*w4.x; acc[3][o4*4+1] += v11*w4.y;
                        acc[3][o4*4+2] += v11*w4.z; acc[3][o4*4+3] += v11*w4.w;
                    }
                }
            }
        }
    }

    #pragma unroll
    for (int p = 0; p < 4; p++){
        const int y = y0 + py + (p >> 1);
        const int x = x0 + px + (p & 1);
        int diff = y - x; if (diff < 0) diff = -diff; if (diff < 1) diff = 1;
        const float len = (float)diff;
        float4* op = reinterpret_cast<float4*>(&out[((y*N_ + x)*B_ + b)*O_]);
        #pragma unroll
        for (int o4 = 0; o4 < 4; o4++)
            op[o4] = make_float4(len*acc[p][o4*4+0], len*acc[p][o4*4+1],
                                 len*acc[p][o4*4+2], len*acc[p][o4*4+3]);
    }
}

// ---------------- skip MLP ---------------------------------------------------
__global__ void skip_kernel(const float* __restrict__ x,
    const float* __restrict__ sw1, const float* __restrict__ sb1,
    const float* __restrict__ sw2, const float* __restrict__ sb2,
    const float* __restrict__ sw3, const float* __restrict__ sb3,
    float* __restrict__ out){
    __shared__ float sFeat[384];
    __shared__ float sH1[64];
    __shared__ float sH2[64];
    const int i = blockIdx.x, b = blockIdx.y;
    const int t = threadIdx.x;
    {
        float xa = x[(i*B_ + b)*D_ + t];
        float xb = x[((i+1)*B_ + b)*D_ + t];
        sFeat[t] = xa; sFeat[128 + t] = xb; sFeat[256 + t] = xa*xb;
    }
    __syncthreads();
    if (t < 64){
        float a = sb1[t];
        #pragma unroll 4
        for (int k = 0; k < 384; k++) a += sFeat[k]*sw1[t*384 + k];
        sH1[t] = gelu_f(a);
    }
    __syncthreads();
    if (t < 64){
        float a = sb2[t];
        #pragma unroll 4
        for (int k = 0; k < 64; k++) a += sH1[k]*sw2[t*64 + k];
        sH2[t] = gelu_f(a);
    }
    __syncthreads();
    if (t < 16){
        float a = sb3[t];
        #pragma unroll 4
        for (int k = 0; k < 64; k++) a += sH2[k]*sw3[t*64 + k];
        out[(i*B_ + b)*O_ + t] = a;
    }
}

// ---------------------------------------------------------------------------
extern "C" void kernel_launch(void* const* d_in, const int* in_sizes, int n_in,
                              void* d_out, int out_size){
    const float* x   = (const float*)d_in[0];
    const float* w1  = (const float*)d_in[1];
    const float* b1  = (const float*)d_in[2];
    const float* w2  = (const float*)d_in[3];
    const float* b2  = (const float*)d_in[4];
    const float* w3  = (const float*)d_in[5];
    const float* b3  = (const float*)d_in[6];
    const float* sw1 = (const float*)d_in[7];
    const float* sb1 = (const float*)d_in[8];
    const float* sw2 = (const float*)d_in[9];
    const float* sb2 = (const float*)d_in[10];
    const float* sw3 = (const float*)d_in[11];
    const float* sb3 = (const float*)d_in[12];
    const float* cw1 = (const float*)d_in[13];
    const float* cb1 = (const float*)d_in[14];
    const float* cw2 = (const float*)d_in[15];
    const float* cb2 = (const float*)d_in[16];
    float* out = (float*)d_out;

    const int pre_smem = 16512*4;
    cudaFuncSetAttribute(precompute_kernel, cudaFuncAttributeMaxDynamicSharedMemorySize, pre_smem);
    cudaFuncSetAttribute(pair_mlp_mma, cudaFuncAttributeMaxDynamicSharedMemorySize, PAIR_SMEM_BYTES);
    cudaFuncSetAttribute(conv1_kernel, cudaFuncAttributeMaxDynamicSharedMemorySize, C1_SMEM_BYTES);
    cudaFuncSetAttribute(conv2_kernel, cudaFuncAttributeMaxDynamicSharedMemorySize, C2_SMEM_BYTES);

    scan_kernel<<<256, 512>>>(x);
    zero_S0<<<2048, 256>>>();
    precompute_kernel<<<dim3(9, B_), 256, pre_smem>>>(x, w1);

    pair_mlp_mma<<<dim3(768, 2), 256, PAIR_SMEM_BYTES>>>(x, w1, b1, w2, b2, w3, b3);

    dim3 blk(16, 16);
    conv1_kernel<<<dim3(17, 17, B_*4), blk, C1_SMEM_BYTES>>>(cw1, cb1);
    conv2_kernel<<<dim3(16, 16, B_), blk, C2_SMEM_BYTES>>>(cw2, cb2, cb1, out);

    skip_kernel<<<dim3(N_-1, 2), 128>>>(x, sw1, sb1, sw2, sb2, sw3, sb3,
                                        out + (size_t)N_*N_*B_*O_);
}

// round 11
// speedup vs baseline: 3.2046x; 1.2406x over previous
#include <cuda_runtime.h>
#include <math.h>
#include <stdint.h>

#define N_   512
#define B_   2
#define D_   128
#define O_   16
#define H_   64
#define CH_  48
#define SIXD 768
#define BD   (B_*D_)        // 256

// ---------------- scratch ----------------------------------------------------
__device__ float g_cum1[(N_+1)*BD];
__device__ float g_cum2[(N_+1)*BD];
__device__ float g_cum3[(N_+1)*BD];
__device__ float g_S0[B_*O_*N_*N_];      // [b][o][i][j]
__device__ float g_u0[B_*N_*H_];
__device__ float g_v [B_*N_*H_];
__device__ float g_U [B_*(N_+1)*H_];

__device__ __forceinline__ float gelu_f(float v){
    return 0.5f * v * (1.0f + erff(v * 0.70710678118654752f));
}
__device__ __forceinline__ uint32_t f2tf32(float v){
    uint32_t r;
    asm("cvt.rna.tf32.f32 %0, %1;" : "=r"(r) : "f"(v));
    return r;
}
__device__ __forceinline__ void mma_tf32(float* c,
    uint32_t a0, uint32_t a1, uint32_t a2, uint32_t a3, uint32_t b0, uint32_t b1)
{
    asm volatile(
        "mma.sync.aligned.m16n8k8.row.col.f32.tf32.tf32.f32 "
        "{%0,%1,%2,%3}, {%4,%5,%6,%7}, {%8,%9}, {%0,%1,%2,%3};"
        : "+f"(c[0]), "+f"(c[1]), "+f"(c[2]), "+f"(c[3])
        : "r"(a0), "r"(a1), "r"(a2), "r"(a3), "r"(b0), "r"(b1));
}

// ---------------- parallel prefix sums ---------------------------------------
__global__ void __launch_bounds__(512)
scan_kernel(const float* __restrict__ x){
    __shared__ float s1[512], s2[512], s3[512];
    const int bd = blockIdx.x;
    const int n  = threadIdx.x;
    float v = x[n*BD + bd];
    float a = v, bb = v*v, c = v*v*v;
    s1[n] = a; s2[n] = bb; s3[n] = c;
    #pragma unroll
    for (int off = 1; off < 512; off <<= 1){
        __syncthreads();
        float ta = 0.f, tb = 0.f, tc = 0.f;
        if (n >= off){ ta = s1[n-off]; tb = s2[n-off]; tc = s3[n-off]; }
        __syncthreads();
        if (n >= off){
            a += ta; bb += tb; c += tc;
            s1[n] = a; s2[n] = bb; s3[n] = c;
        }
    }
    g_cum1[(n+1)*BD + bd] = a;
    g_cum2[(n+1)*BD + bd] = bb;
    g_cum3[(n+1)*BD + bd] = c;
    if (n == 0){ g_cum1[bd] = 0.f; g_cum2[bd] = 0.f; g_cum3[bd] = 0.f; }
}

__global__ void zero_S0(){
    int i = blockIdx.x*blockDim.x + threadIdx.x;
    int stride = gridDim.x*blockDim.x;
    float4* p = reinterpret_cast<float4*>(g_S0);
    const int n4 = (B_*O_*N_*N_)/4;
    for (; i < n4; i += stride) p[i] = make_float4(0.f,0.f,0.f,0.f);
}

// ------- precompute u0, v, U (fp32 exact) ------------------------------------
__global__ void __launch_bounds__(256)
precompute_kernel(const float* __restrict__ x, const float* __restrict__ w1){
    extern __shared__ float ps[];
    float* sX = ps;            // 64 x 129
    float* sWt = ps + 8256;    // 64 x 129
    const int n0 = blockIdx.x*64;
    const int b  = blockIdx.y;
    const int t  = threadIdx.x;
    const int tr = t >> 4, tc = t & 15;

    float accA[16], accB[16], accU[16];
    #pragma unroll
    for (int q = 0; q < 16; q++){ accA[q]=0.f; accB[q]=0.f; accU[q]=0.f; }

    for (int cc = 0; cc < 5; cc++){
        __syncthreads();
        const int col0 = (cc == 0) ? 0 : (cc == 1) ? 128 : (cc + 1)*128;
        for (int idx = t; idx < 64*128; idx += 256){
            int h = idx >> 7, d = idx & 127;
            sWt[h*129 + d] = w1[h*SIXD + col0 + d];
        }
        for (int idx = t; idx < 64*128; idx += 256){
            int r = idx >> 7, d = idx & 127;
            int n = n0 + r;
            float v = 0.f;
            if (cc < 2){
                if (n < N_) v = x[(n*B_ + b)*D_ + d];
            } else {
                const float* src = (cc == 2) ? g_cum1 : (cc == 3) ? g_cum2 : g_cum3;
                if (n <= N_) v = src[n*BD + b*D_ + d];
            }
            sX[r*129 + d] = v;
        }
        __syncthreads();

        float* accp = (cc == 0) ? accA : (cc == 1) ? accB : accU;
        #pragma unroll 4
        for (int d = 0; d < 128; d++){
            float fv[4], wv[4];
            #pragma unroll
            for (int a = 0; a < 4; a++) fv[a] = sX[(tr*4 + a)*129 + d];
            #pragma unroll
            for (int q = 0; q < 4; q++) wv[q] = sWt[(tc*4 + q)*129 + d];
            #pragma unroll
            for (int a = 0; a < 4; a++)
                #pragma unroll
                for (int q = 0; q < 4; q++)
                    accp[a*4+q] += fv[a]*wv[q];
        }
    }

    #pragma unroll
    for (int a = 0; a < 4; a++){
        int n = n0 + tr*4 + a;
        #pragma unroll
        for (int q = 0; q < 4; q++){
            int h = tc*4 + q;
            if (n < N_){
                g_u0[(b*N_ + n)*H_ + h] = accA[a*4+q];
                g_v [(b*N_ + n)*H_ + h] = accB[a*4+q];
            }
            if (n <= N_)
                g_U[(b*(N_+1) + n)*H_ + h] = accU[a*4+q];
        }
    }
}

// ---------------- pair MLP (round-9 shape: 128 rows, 16 rows/warp) -----------
#define SF_F    0        // 128 x 132
#define SW_F    16896    // 64 x 132
#define XI_F    25344
#define INVL_F  25472
#define PRE_F   25600
#define UI1_F   25664
#define B2_F    25728
#define B3_F    25792
#define PAIR_SMEM_F 25808
#define PAIR_SMEM_BYTES (PAIR_SMEM_F*4)

__global__ void __launch_bounds__(256)
pair_mlp_mma(const float* __restrict__ x,
    const float* __restrict__ w1, const float* __restrict__ b1,
    const float* __restrict__ w2, const float* __restrict__ b2,
    const float* __restrict__ w3, const float* __restrict__ b3)
{
    extern __shared__ float sm[];
    float* sF = sm + SF_F;
    float* sW = sm + SW_F;

    const int t    = threadIdx.x;
    const int warp = t >> 5;
    const int lane = t & 31;
    const int qrow = lane >> 2;
    const int qcol = lane & 3;
    const int r0   = warp*16 + qrow;

    const int tile = blockIdx.x;
    const int b    = blockIdx.y;
    const int g    = (tile >= 768) ? 3 : (tile >= 384) ? 2 : (tile >= 128) ? 1 : 0;
    const int rem  = tile - 64*g*(g+1);
    const int i    = 128*g + rem/(g+1);
    const int j0   = 128*(rem % (g+1));

    if (t < 128){
        sm[XI_F + t] = x[(i*B_ + b)*D_ + t];
        int j = j0 + t;
        sm[INVL_F + t] = (j <= i) ? 1.0f/(float)(i - j + 1) : 0.0f;
    }
    if (t < 64){
        sm[PRE_F + t] = b1[t] + g_u0[(b*N_ + i)*H_ + t];
        sm[UI1_F + t] = g_U[(b*(N_+1) + i + 1)*H_ + t];
        sm[B2_F  + t] = b2[t];
    }
    if (t < 16) sm[B3_F + t] = b3[t];
    __syncthreads();

    for (int idx = t; idx < 128*32; idx += 256){
        int r = idx >> 5, d4 = idx & 31;
        float4 v = *reinterpret_cast<const float4*>(&x[((j0 + r)*B_ + b)*D_ + d4*4]);
        float4 o;
        o.x = __uint_as_float(f2tf32(v.x)); o.y = __uint_as_float(f2tf32(v.y));
        o.z = __uint_as_float(f2tf32(v.z)); o.w = __uint_as_float(f2tf32(v.w));
        *reinterpret_cast<float4*>(&sF[r*132 + d4*4]) = o;
    }
    for (int idx = t; idx < 64*32; idx += 256){
        int h = idx >> 5, d4 = idx & 31;
        float4 wv = *reinterpret_cast<const float4*>(&w1[h*SIXD + 256 + d4*4]);
        float4 xi = *reinterpret_cast<const float4*>(&sm[XI_F + d4*4]);
        float4 o;
        o.x = __uint_as_float(f2tf32(wv.x*xi.x)); o.y = __uint_as_float(f2tf32(wv.y*xi.y));
        o.z = __uint_as_float(f2tf32(wv.z*xi.z)); o.w = __uint_as_float(f2tf32(wv.w*xi.w));
        *reinterpret_cast<float4*>(&sW[h*132 + d4*4]) = o;
    }
    __syncthreads();

    float acc[32];
    #pragma unroll
    for (int q = 0; q < 32; q++) acc[q] = 0.f;
    {
        const float* pa = sF + r0*132 + qcol;
        const float* pw = sW + qrow*132 + qcol;
        #pragma unroll
        for (int ks = 0; ks < 16; ks++){
            const int kb = ks*8;
            uint32_t a0 = __float_as_uint(pa[kb]);
            uint32_t a1 = __float_as_uint(pa[kb + 8*132]);
            uint32_t a2 = __float_as_uint(pa[kb + 4]);
            uint32_t a3 = __float_as_uint(pa[kb + 8*132 + 4]);
            #pragma unroll
            for (int nt = 0; nt < 8; nt++){
                uint32_t b0 = __float_as_uint(pw[nt*8*132 + kb]);
                uint32_t b1v= __float_as_uint(pw[nt*8*132 + kb + 4]);
                mma_tf32(acc + nt*4, a0, a1, a2, a3, b0, b1v);
            }
        }
    }
    __syncthreads();

    // layer-1 epilogue
    {
        const int jA = j0 + r0, jB = j0 + r0 + 8;
        const float ilA = sm[INVL_F + r0], ilB = sm[INVL_F + r0 + 8];
        const float* vA = &g_v[(b*N_ + jA)*H_];
        const float* vB = &g_v[(b*N_ + jB)*H_];
        const float* uA = &g_U[(b*(N_+1) + jA)*H_];
        const float* uB = &g_U[(b*(N_+1) + jB)*H_];
        #pragma unroll
        for (int nt = 0; nt < 8; nt++){
            const int col = nt*8 + qcol*2;
            float pre0 = sm[PRE_F + col], pre1 = sm[PRE_F + col + 1];
            float ui0  = sm[UI1_F + col], ui1  = sm[UI1_F + col + 1];
            float2 vv, uu;
            vv = *reinterpret_cast<const float2*>(vA + col);
            uu = *reinterpret_cast<const float2*>(uA + col);
            sF[(r0    )*68 + col    ] = __uint_as_float(f2tf32(gelu_f(acc[nt*4+0] + pre0 + vv.x + ilA*(ui0 - uu.x))));
            sF[(r0    )*68 + col + 1] = __uint_as_float(f2tf32(gelu_f(acc[nt*4+1] + pre1 + vv.y + ilA*(ui1 - uu.y))));
            vv = *reinterpret_cast<const float2*>(vB + col);
            uu = *reinterpret_cast<const float2*>(uB + col);
            sF[(r0 + 8)*68 + col    ] = __uint_as_float(f2tf32(gelu_f(acc[nt*4+2] + pre0 + vv.x + ilB*(ui0 - uu.x))));
            sF[(r0 + 8)*68 + col + 1] = __uint_as_float(f2tf32(gelu_f(acc[nt*4+3] + pre1 + vv.y + ilB*(ui1 - uu.y))));
        }
    }
    for (int idx = t; idx < 64*64; idx += 256){
        int h = idx >> 6, k = idx & 63;
        sW[h*132 + k] = __uint_as_float(f2tf32(w2[h*64 + k]));
    }
    __syncthreads();

    #pragma unroll
    for (int q = 0; q < 32; q++) acc[q] = 0.f;
    {
        const float* pa = sF + r0*68 + qcol;
        const float* pw = sW + qrow*132 + qcol;
        #pragma unroll
        for (int ks = 0; ks < 8; ks++){
            const int kb = ks*8;
            uint32_t a0 = __float_as_uint(pa[kb]);
            uint32_t a1 = __float_as_uint(pa[kb + 8*68]);
            uint32_t a2 = __float_as_uint(pa[kb + 4]);
            uint32_t a3 = __float_as_uint(pa[kb + 8*68 + 4]);
            #pragma unroll
            for (int nt = 0; nt < 8; nt++){
                uint32_t b0 = __float_as_uint(pw[nt*8*132 + kb]);
                uint32_t b1v= __float_as_uint(pw[nt*8*132 + kb + 4]);
                mma_tf32(acc + nt*4, a0, a1, a2, a3, b0, b1v);
            }
        }
    }
    __syncthreads();

    #pragma unroll
    for (int nt = 0; nt < 8; nt++){
        const int col = nt*8 + qcol*2;
        sF[(r0    )*68 + col    ] = gelu_f(acc[nt*4+0] + sm[B2_F + col    ]);
        sF[(r0    )*68 + col + 1] = gelu_f(acc[nt*4+1] + sm[B2_F + col + 1]);
        sF[(r0 + 8)*68 + col    ] = gelu_f(acc[nt*4+2] + sm[B2_F + col    ]);
        sF[(r0 + 8)*68 + col + 1] = gelu_f(acc[nt*4+3] + sm[B2_F + col + 1]);
    }
    for (int idx = t; idx < 16*64; idx += 256){
        int o = idx >> 6, k = idx & 63;
        sW[o*68 + k] = w3[o*64 + k];
    }
    __syncthreads();

    {
        const int r  = t >> 1;
        const int o0 = (t & 1)*8;
        float a3[8];
        #pragma unroll
        for (int q = 0; q < 8; q++) a3[q] = 0.f;
        #pragma unroll
        for (int k4 = 0; k4 < 16; k4++){
            float4 h4 = *reinterpret_cast<const float4*>(&sF[r*68 + k4*4]);
            #pragma unroll
            for (int q = 0; q < 8; q++){
                float4 w4 = *reinterpret_cast<const float4*>(&sW[(o0+q)*68 + k4*4]);
                a3[q] += h4.x*w4.x + h4.y*w4.y + h4.z*w4.z + h4.w*w4.w;
            }
        }
        const int j = j0 + r;
        if (j <= i){
            #pragma unroll
            for (int q = 0; q < 8; q++)
                g_S0[((b*O_ + o0 + q)*N_ + i)*N_ + j] = a3[q] + sm[B3_F + o0 + q];
        }
    }
}

// ======= FUSED conv1(pad2)+gelu+conv2(valid)+bias+len-scale+permute ==========
// grid (16,16,B), block (16,16). 6 groups of 8 conv1-out channels.
// smem floats:
#define FC_S0_F   0                 // 16 x 36 x 37 = 21312
#define FC_MID_F  21312             // 8 x 34 x 36  = 9792
#define FC_W1_F   31104             // 1152: [(oin*9+kk)*8 + cl]
#define FC_W2_F   32256             // 1152: [(ci*9+kk)*16 + o]
#define FC_B1_F   33408             // 8
#define FC_B2_F   33416             // 16
#define FC_K2_F   33432             // 16
#define FC_SMEM_F 33448
#define FC_SMEM_BYTES (FC_SMEM_F*4)

__global__ void __launch_bounds__(256)
fused_conv_kernel(const float* __restrict__ cw1, const float* __restrict__ cb1,
                  const float* __restrict__ cw2, const float* __restrict__ cb2,
                  float* __restrict__ out){
    extern __shared__ float smv[];
    float* sS0 = smv + FC_S0_F;
    float* sMid= smv + FC_MID_F;
    float* sW1 = smv + FC_W1_F;
    float* sW2 = smv + FC_W2_F;
    float* sB1 = smv + FC_B1_F;
    float* sB2 = smv + FC_B2_F;
    float* sK2 = smv + FC_K2_F;
    const int b  = blockIdx.z;
    const int y0 = blockIdx.y*32, x0 = blockIdx.x*32;
    const int tx = threadIdx.x, ty = threadIdx.y;
    const int t  = ty*16 + tx;

    // --- constant-region skip (S0 window all zero) ---------------------------
    if (x0 >= y0 + 64){
        if (t < 16){
            float s = cb2[t];
            for (int c = 0; c < CH_; c++){
                float gg = gelu_f(cb1[c]);
                float ws = 0.f;
                #pragma unroll
                for (int kk = 0; kk < 9; kk++) ws += cw2[t*432 + c*9 + kk];
                s += ws*gg;
            }
            sK2[t] = s;
        }
        __syncthreads();
        #pragma unroll
        for (int p = 0; p < 4; p++){
            const int y = y0 + 2*ty + (p >> 1);
            const int x = x0 + 2*tx + (p & 1);
            const float len = (float)(x - y);
            float4* op = reinterpret_cast<float4*>(&out[((y*N_ + x)*B_ + b)*O_]);
            #pragma unroll
            for (int o4 = 0; o4 < 4; o4++)
                op[o4] = make_float4(len*sK2[o4*4+0], len*sK2[o4*4+1],
                                     len*sK2[o4*4+2], len*sK2[o4*4+3]);
        }
        return;
    }

    // --- stage S0 window: 16 ch x 36x36 (origin y0-2, x0-2), zero-padded -----
    for (int idx = t; idx < 16*36*36; idx += 256){
        int ch = idx/1296, p = idx%1296;
        int iy = p/36, ix = p%36;
        int yy = y0 - 2 + iy, xx = x0 - 2 + ix;
        float v = 0.f;
        if (yy >= 0 && yy < N_ && xx >= 0 && xx < N_)
            v = g_S0[((b*O_ + ch)*N_ + yy)*N_ + xx];
        sS0[ch*1332 + iy*37 + ix] = v;
    }
    if (t < 16) sB2[t] = cb2[t];

    float acc2[4][16];
    #pragma unroll
    for (int p = 0; p < 4; p++)
        #pragma unroll
        for (int o = 0; o < 16; o++) acc2[p][o] = 0.f;

    for (int cg = 0; cg < 6; cg++){
        __syncthreads();     // prior conv2 reads + S0 staging done
        // stage group weights
        for (int idx = t; idx < 8*144; idx += 256){
            int cl = idx/144, rem = idx%144;          // rem = oin*9+kk
            sW1[rem*8 + cl] = cw1[(cg*8 + cl)*144 + rem];
        }
        for (int idx = t; idx < 16*72; idx += 256){
            int o = idx/72, rem = idx%72;             // rem = ci*9+kk
            sW2[rem*16 + o] = cw2[o*432 + cg*72 + rem];
        }
        if (t < 8) sB1[t] = cb1[cg*8 + t];
        __syncthreads();

        // conv1: compute Mid (8 ch, 34x34) — 2x2 quads, 17x17 = 289 quads
        for (int q = t; q < 289; q += 256){
            const int my = 2*(q/17), mx = 2*(q%17);
            float a1[4][8];
            #pragma unroll
            for (int p = 0; p < 4; p++)
                #pragma unroll
                for (int cl = 0; cl < 8; cl++) a1[p][cl] = sB1[cl];
            for (int oin = 0; oin < 16; oin++){
                const float* pI = &sS0[oin*1332 + my*37 + mx];
                const float* pW = &sW1[oin*72];
                #pragma unroll
                for (int ky = 0; ky < 3; ky++){
                    #pragma unroll
                    for (int kx = 0; kx < 3; kx++){
                        float v00 = pI[ky*37 + kx],      v01 = pI[ky*37 + kx + 1];
                        float v10 = pI[ky*37 + kx + 37], v11 = pI[ky*37 + kx + 38];
                        const float4* wp = reinterpret_cast<const float4*>(pW + (ky*3 + kx)*8);
                        #pragma unroll
                        for (int c4 = 0; c4 < 2; c4++){
                            float4 w4 = wp[c4];
                            a1[0][c4*4+0] += v00*w4.x; a1[0][c4*4+1] += v00*w4.y;
                            a1[0][c4*4+2] += v00*w4.z; a1[0][c4*4+3] += v00*w4.w;
                            a1[1][c4*4+0] += v01*w4.x; a1[1][c4*4+1] += v01*w4.y;
                            a1[1][c4*4+2] += v01*w4.z; a1[1][c4*4+3] += v01*w4.w;
                            a1[2][c4*4+0] += v10*w4.x; a1[2][c4*4+1] += v10*w4.y;
                            a1[2][c4*4+2] += v10*w4.z; a1[2][c4*4+3] += v10*w4.w;
                            a1[3][c4*4+0] += v11*w4.x; a1[3][c4*4+1] += v11*w4.y;
                            a1[3][c4*4+2] += v11*w4.z; a1[3][c4*4+3] += v11*w4.w;
                        }
                    }
                }
            }
            #pragma unroll
            for (int p = 0; p < 4; p++){
                const int yy = my + (p >> 1), xx = mx + (p & 1);
                #pragma unroll
                for (int cl = 0; cl < 8; cl++)
                    sMid[cl*1224 + yy*36 + xx] = gelu_f(a1[p][cl]);
            }
        }
        __syncthreads();

        // conv2 accumulate from Mid (8 in-ch), 2x2 px, all 16 out-ch
        for (int ci = 0; ci < 8; ci++){
            const float* pI = &sMid[ci*1224 + 2*ty*36 + 2*tx];
            const float* pW = &sW2[ci*144];
            #pragma unroll
            for (int ky = 0; ky < 3; ky++){
                #pragma unroll
                for (int kx = 0; kx < 3; kx++){
                    float v00 = pI[ky*36 + kx],      v01 = pI[ky*36 + kx + 1];
                    float v10 = pI[ky*36 + kx + 36], v11 = pI[ky*36 + kx + 37];
                    const float4* wp = reinterpret_cast<const float4*>(pW + (ky*3 + kx)*16);
                    #pragma unroll
                    for (int o4 = 0; o4 < 4; o4++){
                        float4 w4 = wp[o4];
                        acc2[0][o4*4+0] += v00*w4.x; acc2[0][o4*4+1] += v00*w4.y;
                        acc2[0][o4*4+2] += v00*w4.z; acc2[0][o4*4+3] += v00*w4.w;
                        acc2[1][o4*4+0] += v01*w4.x; acc2[1][o4*4+1] += v01*w4.y;
                        acc2[1][o4*4+2] += v01*w4.z; acc2[1][o4*4+3] += v01*w4.w;
                        acc2[2][o4*4+0] += v10*w4.x; acc2[2][o4*4+1] += v10*w4.y;
                        acc2[2][o4*4+2] += v10*w4.z; acc2[2][o4*4+3] += v10*w4.w;
                        acc2[3][o4*4+0] += v11*w4.x; acc2[3][o4*4+1] += v11*w4.y;
                        acc2[3][o4*4+2] += v11*w4.z; acc2[3][o4*4+3] += v11*w4.w;
                    }
                }
            }
        }
    }

    #pragma unroll
    for (int p = 0; p < 4; p++){
        const int y = y0 + 2*ty + (p >> 1);
        const int x = x0 + 2*tx + (p & 1);
        int diff = y - x; if (diff < 0) diff = -diff; if (diff < 1) diff = 1;
        const float len = (float)diff;
        float4* op = reinterpret_cast<float4*>(&out[((y*N_ + x)*B_ + b)*O_]);
        #pragma unroll
        for (int o4 = 0; o4 < 4; o4++)
            op[o4] = make_float4(len*(acc2[p][o4*4+0] + sB2[o4*4+0]),
                                 len*(acc2[p][o4*4+1] + sB2[o4*4+1]),
                                 len*(acc2[p][o4*4+2] + sB2[o4*4+2]),
                                 len*(acc2[p][o4*4+3] + sB2[o4*4+3]));
    }
}

// ---------------- skip MLP ---------------------------------------------------
__global__ void skip_kernel(const float* __restrict__ x,
    const float* __restrict__ sw1, const float* __restrict__ sb1,
    const float* __restrict__ sw2, const float* __restrict__ sb2,
    const float* __restrict__ sw3, const float* __restrict__ sb3,
    float* __restrict__ out){
    __shared__ float sFeat[384];
    __shared__ float sH1[64];
    __shared__ float sH2[64];
    const int i = blockIdx.x, b = blockIdx.y;
    const int t = threadIdx.x;
    {
        float xa = x[(i*B_ + b)*D_ + t];
        float xb = x[((i+1)*B_ + b)*D_ + t];
        sFeat[t] = xa; sFeat[128 + t] = xb; sFeat[256 + t] = xa*xb;
    }
    __syncthreads();
    if (t < 64){
        float a = sb1[t];
        #pragma unroll 4
        for (int k = 0; k < 384; k++) a += sFeat[k]*sw1[t*384 + k];
        sH1[t] = gelu_f(a);
    }
    __syncthreads();
    if (t < 64){
        float a = sb2[t];
        #pragma unroll 4
        for (int k = 0; k < 64; k++) a += sH1[k]*sw2[t*64 + k];
        sH2[t] = gelu_f(a);
    }
    __syncthreads();
    if (t < 16){
        float a = sb3[t];
        #pragma unroll 4
        for (int k = 0; k < 64; k++) a += sH2[k]*sw3[t*64 + k];
        out[(i*B_ + b)*O_ + t] = a;
    }
}

// ---------------------------------------------------------------------------
extern "C" void kernel_launch(void* const* d_in, const int* in_sizes, int n_in,
                              void* d_out, int out_size){
    const float* x   = (const float*)d_in[0];
    const float* w1  = (const float*)d_in[1];
    const float* b1  = (const float*)d_in[2];
    const float* w2  = (const float*)d_in[3];
    const float* b2  = (const float*)d_in[4];
    const float* w3  = (const float*)d_in[5];
    const float* b3  = (const float*)d_in[6];
    const float* sw1 = (const float*)d_in[7];
    const float* sb1 = (const float*)d_in[8];
    const float* sw2 = (const float*)d_in[9];
    const float* sb2 = (const float*)d_in[10];
    const float* sw3 = (const float*)d_in[11];
    const float* sb3 = (const float*)d_in[12];
    const float* cw1 = (const float*)d_in[13];
    const float* cb1 = (const float*)d_in[14];
    const float* cw2 = (const float*)d_in[15];
    const float* cb2 = (const float*)d_in[16];
    float* out = (float*)d_out;

    const int pre_smem = 16512*4;
    cudaFuncSetAttribute(precompute_kernel, cudaFuncAttributeMaxDynamicSharedMemorySize, pre_smem);
    cudaFuncSetAttribute(pair_mlp_mma, cudaFuncAttributeMaxDynamicSharedMemorySize, PAIR_SMEM_BYTES);
    cudaFuncSetAttribute(fused_conv_kernel, cudaFuncAttributeMaxDynamicSharedMemorySize, FC_SMEM_BYTES);

    scan_kernel<<<256, 512>>>(x);
    zero_S0<<<2048, 256>>>();
    precompute_kernel<<<dim3(9, B_), 256, pre_smem>>>(x, w1);

    pair_mlp_mma<<<dim3(1280, 2), 256, PAIR_SMEM_BYTES>>>(x, w1, b1, w2, b2, w3, b3);

    dim3 blk(16, 16);
    fused_conv_kernel<<<dim3(16, 16, B_), blk, FC_SMEM_BYTES>>>(cw1, cb1, cw2, cb2, out);

    skip_kernel<<<dim3(N_-1, 2), 128>>>(x, sw1, sb1, sw2, sb2, sw3, sb3,
                                        out + (size_t)N_*N_*B_*O_);
}

// round 15
// speedup vs baseline: 4.4396x; 1.3854x over previous
#include <cuda_runtime.h>
#include <math.h>
#include <stdint.h>

#define N_   512
#define B_   2
#define D_   128
#define O_   16
#define H_   64
#define CH_  48
#define SIXD 768
#define BD   (B_*D_)        // 256

// ---------------- scratch ----------------------------------------------------
__device__ float g_cum1[(N_+1)*BD];
__device__ float g_cum2[(N_+1)*BD];
__device__ float g_cum3[(N_+1)*BD];
__device__ float g_S0[B_*O_*N_*N_];      // [b][o][i][j]
__device__ float g_u0[B_*N_*H_];
__device__ float g_v [B_*N_*H_];
__device__ float g_U [B_*(N_+1)*H_];

__device__ __forceinline__ float gelu_f(float v){
    return 0.5f * v * (1.0f + erff(v * 0.70710678118654752f));
}
__device__ __forceinline__ uint32_t f2tf32(float v){
    uint32_t r;
    asm("cvt.rna.tf32.f32 %0, %1;" : "=r"(r) : "f"(v));
    return r;
}
__device__ __forceinline__ float tf32f(float v){
    return __uint_as_float(f2tf32(v));
}
__device__ __forceinline__ void mma_tf32(float* c,
    uint32_t a0, uint32_t a1, uint32_t a2, uint32_t a3, uint32_t b0, uint32_t b1)
{
    asm volatile(
        "mma.sync.aligned.m16n8k8.row.col.f32.tf32.tf32.f32 "
        "{%0,%1,%2,%3}, {%4,%5,%6,%7}, {%8,%9}, {%0,%1,%2,%3};"
        : "+f"(c[0]), "+f"(c[1]), "+f"(c[2]), "+f"(c[3])
        : "r"(a0), "r"(a1), "r"(a2), "r"(a3), "r"(b0), "r"(b1));
}

// ---------------- parallel prefix sums ---------------------------------------
__global__ void __launch_bounds__(512)
scan_kernel(const float* __restrict__ x){
    __shared__ float s1[512], s2[512], s3[512];
    const int bd = blockIdx.x;
    const int n  = threadIdx.x;
    float v = x[n*BD + bd];
    float a = v, bb = v*v, c = v*v*v;
    s1[n] = a; s2[n] = bb; s3[n] = c;
    #pragma unroll
    for (int off = 1; off < 512; off <<= 1){
        __syncthreads();
        float ta = 0.f, tb = 0.f, tc = 0.f;
        if (n >= off){ ta = s1[n-off]; tb = s2[n-off]; tc = s3[n-off]; }
        __syncthreads();
        if (n >= off){
            a += ta; bb += tb; c += tc;
            s1[n] = a; s2[n] = bb; s3[n] = c;
        }
    }
    g_cum1[(n+1)*BD + bd] = a;
    g_cum2[(n+1)*BD + bd] = bb;
    g_cum3[(n+1)*BD + bd] = c;
    if (n == 0){ g_cum1[bd] = 0.f; g_cum2[bd] = 0.f; g_cum3[bd] = 0.f; }
}

__global__ void zero_S0(){
    int i = blockIdx.x*blockDim.x + threadIdx.x;
    int stride = gridDim.x*blockDim.x;
    float4* p = reinterpret_cast<float4*>(g_S0);
    const int n4 = (B_*O_*N_*N_)/4;
    for (; i < n4; i += stride) p[i] = make_float4(0.f,0.f,0.f,0.f);
}

// ------- precompute u0, v, U (fp32 exact) ------------------------------------
__global__ void __launch_bounds__(256)
precompute_kernel(const float* __restrict__ x, const float* __restrict__ w1){
    extern __shared__ float ps[];
    float* sX = ps;            // 64 x 129
    float* sWt = ps + 8256;    // 64 x 129
    const int n0 = blockIdx.x*64;
    const int b  = blockIdx.y;
    const int t  = threadIdx.x;
    const int tr = t >> 4, tc = t & 15;

    float accA[16], accB[16], accU[16];
    #pragma unroll
    for (int q = 0; q < 16; q++){ accA[q]=0.f; accB[q]=0.f; accU[q]=0.f; }

    for (int cc = 0; cc < 5; cc++){
        __syncthreads();
        const int col0 = (cc == 0) ? 0 : (cc == 1) ? 128 : (cc + 1)*128;
        for (int idx = t; idx < 64*128; idx += 256){
            int h = idx >> 7, d = idx & 127;
            sWt[h*129 + d] = w1[h*SIXD + col0 + d];
        }
        for (int idx = t; idx < 64*128; idx += 256){
            int r = idx >> 7, d = idx & 127;
            int n = n0 + r;
            float v = 0.f;
            if (cc < 2){
                if (n < N_) v = x[(n*B_ + b)*D_ + d];
            } else {
                const float* src = (cc == 2) ? g_cum1 : (cc == 3) ? g_cum2 : g_cum3;
                if (n <= N_) v = src[n*BD + b*D_ + d];
            }
            sX[r*129 + d] = v;
        }
        __syncthreads();

        float* accp = (cc == 0) ? accA : (cc == 1) ? accB : accU;
        #pragma unroll 4
        for (int d = 0; d < 128; d++){
            float fv[4], wv[4];
            #pragma unroll
            for (int a = 0; a < 4; a++) fv[a] = sX[(tr*4 + a)*129 + d];
            #pragma unroll
            for (int q = 0; q < 4; q++) wv[q] = sWt[(tc*4 + q)*129 + d];
            #pragma unroll
            for (int a = 0; a < 4; a++)
                #pragma unroll
                for (int q = 0; q < 4; q++)
                    accp[a*4+q] += fv[a]*wv[q];
        }
    }

    #pragma unroll
    for (int a = 0; a < 4; a++){
        int n = n0 + tr*4 + a;
        #pragma unroll
        for (int q = 0; q < 4; q++){
            int h = tc*4 + q;
            if (n < N_){
                g_u0[(b*N_ + n)*H_ + h] = accA[a*4+q];
                g_v [(b*N_ + n)*H_ + h] = accB[a*4+q];
            }
            if (n <= N_)
                g_U[(b*(N_+1) + n)*H_ + h] = accU[a*4+q];
        }
    }
}

// ---------------- pair MLP (unchanged from round 11) -------------------------
#define SF_F    0        // 128 x 132
#define SW_F    16896    // 64 x 132
#define XI_F    25344
#define INVL_F  25472
#define PRE_F   25600
#define UI1_F   25664
#define B2_F    25728
#define B3_F    25792
#define PAIR_SMEM_F 25808
#define PAIR_SMEM_BYTES (PAIR_SMEM_F*4)

__global__ void __launch_bounds__(256)
pair_mlp_mma(const float* __restrict__ x,
    const float* __restrict__ w1, const float* __restrict__ b1,
    const float* __restrict__ w2, const float* __restrict__ b2,
    const float* __restrict__ w3, const float* __restrict__ b3)
{
    extern __shared__ float sm[];
    float* sF = sm + SF_F;
    float* sW = sm + SW_F;

    const int t    = threadIdx.x;
    const int warp = t >> 5;
    const int lane = t & 31;
    const int qrow = lane >> 2;
    const int qcol = lane & 3;
    const int r0   = warp*16 + qrow;

    const int tile = blockIdx.x;
    const int b    = blockIdx.y;
    const int g    = (tile >= 768) ? 3 : (tile >= 384) ? 2 : (tile >= 128) ? 1 : 0;
    const int rem  = tile - 64*g*(g+1);
    const int i    = 128*g + rem/(g+1);
    const int j0   = 128*(rem % (g+1));

    if (t < 128){
        sm[XI_F + t] = x[(i*B_ + b)*D_ + t];
        int j = j0 + t;
        sm[INVL_F + t] = (j <= i) ? 1.0f/(float)(i - j + 1) : 0.0f;
    }
    if (t < 64){
        sm[PRE_F + t] = b1[t] + g_u0[(b*N_ + i)*H_ + t];
        sm[UI1_F + t] = g_U[(b*(N_+1) + i + 1)*H_ + t];
        sm[B2_F  + t] = b2[t];
    }
    if (t < 16) sm[B3_F + t] = b3[t];
    __syncthreads();

    for (int idx = t; idx < 128*32; idx += 256){
        int r = idx >> 5, d4 = idx & 31;
        float4 v = *reinterpret_cast<const float4*>(&x[((j0 + r)*B_ + b)*D_ + d4*4]);
        float4 o;
        o.x = tf32f(v.x); o.y = tf32f(v.y);
        o.z = tf32f(v.z); o.w = tf32f(v.w);
        *reinterpret_cast<float4*>(&sF[r*132 + d4*4]) = o;
    }
    for (int idx = t; idx < 64*32; idx += 256){
        int h = idx >> 5, d4 = idx & 31;
        float4 wv = *reinterpret_cast<const float4*>(&w1[h*SIXD + 256 + d4*4]);
        float4 xi = *reinterpret_cast<const float4*>(&sm[XI_F + d4*4]);
        float4 o;
        o.x = tf32f(wv.x*xi.x); o.y = tf32f(wv.y*xi.y);
        o.z = tf32f(wv.z*xi.z); o.w = tf32f(wv.w*xi.w);
        *reinterpret_cast<float4*>(&sW[h*132 + d4*4]) = o;
    }
    __syncthreads();

    float acc[32];
    #pragma unroll
    for (int q = 0; q < 32; q++) acc[q] = 0.f;
    {
        const float* pa = sF + r0*132 + qcol;
        const float* pw = sW + qrow*132 + qcol;
        #pragma unroll
        for (int ks = 0; ks < 16; ks++){
            const int kb = ks*8;
            uint32_t a0 = __float_as_uint(pa[kb]);
            uint32_t a1 = __float_as_uint(pa[kb + 8*132]);
            uint32_t a2 = __float_as_uint(pa[kb + 4]);
            uint32_t a3 = __float_as_uint(pa[kb + 8*132 + 4]);
            #pragma unroll
            for (int nt = 0; nt < 8; nt++){
                uint32_t b0 = __float_as_uint(pw[nt*8*132 + kb]);
                uint32_t b1v= __float_as_uint(pw[nt*8*132 + kb + 4]);
                mma_tf32(acc + nt*4, a0, a1, a2, a3, b0, b1v);
            }
        }
    }
    __syncthreads();

    {
        const int jA = j0 + r0, jB = j0 + r0 + 8;
        const float ilA = sm[INVL_F + r0], ilB = sm[INVL_F + r0 + 8];
        const float* vA = &g_v[(b*N_ + jA)*H_];
        const float* vB = &g_v[(b*N_ + jB)*H_];
        const float* uA = &g_U[(b*(N_+1) + jA)*H_];
        const float* uB = &g_U[(b*(N_+1) + jB)*H_];
        #pragma unroll
        for (int nt = 0; nt < 8; nt++){
            const int col = nt*8 + qcol*2;
            float pre0 = sm[PRE_F + col], pre1 = sm[PRE_F + col + 1];
            float ui0  = sm[UI1_F + col], ui1  = sm[UI1_F + col + 1];
            float2 vv, uu;
            vv = *reinterpret_cast<const float2*>(vA + col);
            uu = *reinterpret_cast<const float2*>(uA + col);
            sF[(r0    )*68 + col    ] = tf32f(gelu_f(acc[nt*4+0] + pre0 + vv.x + ilA*(ui0 - uu.x)));
            sF[(r0    )*68 + col + 1] = tf32f(gelu_f(acc[nt*4+1] + pre1 + vv.y + ilA*(ui1 - uu.y)));
            vv = *reinterpret_cast<const float2*>(vB + col);
            uu = *reinterpret_cast<const float2*>(uB + col);
            sF[(r0 + 8)*68 + col    ] = tf32f(gelu_f(acc[nt*4+2] + pre0 + vv.x + ilB*(ui0 - uu.x)));
            sF[(r0 + 8)*68 + col + 1] = tf32f(gelu_f(acc[nt*4+3] + pre1 + vv.y + ilB*(ui1 - uu.y)));
        }
    }
    for (int idx = t; idx < 64*64; idx += 256){
        int h = idx >> 6, k = idx & 63;
        sW[h*132 + k] = tf32f(w2[h*64 + k]);
    }
    __syncthreads();

    #pragma unroll
    for (int q = 0; q < 32; q++) acc[q] = 0.f;
    {
        const float* pa = sF + r0*68 + qcol;
        const float* pw = sW + qrow*132 + qcol;
        #pragma unroll
        for (int ks = 0; ks < 8; ks++){
            const int kb = ks*8;
            uint32_t a0 = __float_as_uint(pa[kb]);
            uint32_t a1 = __float_as_uint(pa[kb + 8*68]);
            uint32_t a2 = __float_as_uint(pa[kb + 4]);
            uint32_t a3 = __float_as_uint(pa[kb + 8*68 + 4]);
            #pragma unroll
            for (int nt = 0; nt < 8; nt++){
                uint32_t b0 = __float_as_uint(pw[nt*8*132 + kb]);
                uint32_t b1v= __float_as_uint(pw[nt*8*132 + kb + 4]);
                mma_tf32(acc + nt*4, a0, a1, a2, a3, b0, b1v);
            }
        }
    }
    __syncthreads();

    #pragma unroll
    for (int nt = 0; nt < 8; nt++){
        const int col = nt*8 + qcol*2;
        sF[(r0    )*68 + col    ] = gelu_f(acc[nt*4+0] + sm[B2_F + col    ]);
        sF[(r0    )*68 + col + 1] = gelu_f(acc[nt*4+1] + sm[B2_F + col + 1]);
        sF[(r0 + 8)*68 + col    ] = gelu_f(acc[nt*4+2] + sm[B2_F + col    ]);
        sF[(r0 + 8)*68 + col + 1] = gelu_f(acc[nt*4+3] + sm[B2_F + col + 1]);
    }
    for (int idx = t; idx < 16*64; idx += 256){
        int o = idx >> 6, k = idx & 63;
        sW[o*68 + k] = w3[o*64 + k];
    }
    __syncthreads();

    {
        const int r  = t >> 1;
        const int o0 = (t & 1)*8;
        float a3[8];
        #pragma unroll
        for (int q = 0; q < 8; q++) a3[q] = 0.f;
        #pragma unroll
        for (int k4 = 0; k4 < 16; k4++){
            float4 h4 = *reinterpret_cast<const float4*>(&sF[r*68 + k4*4]);
            #pragma unroll
            for (int q = 0; q < 8; q++){
                float4 w4 = *reinterpret_cast<const float4*>(&sW[(o0+q)*68 + k4*4]);
                a3[q] += h4.x*w4.x + h4.y*w4.y + h4.z*w4.z + h4.w*w4.w;
            }
        }
        const int j = j0 + r;
        if (j <= i){
            #pragma unroll
            for (int q = 0; q < 8; q++)
                g_S0[((b*O_ + o0 + q)*N_ + i)*N_ + j] = a3[q] + sm[B3_F + o0 + q];
        }
    }
}

// ======= FUSED convs via tap-decomposed implicit GEMM (mma.sync tf32) ========
// grid (16,16,B), block 256.  Channel-planar smem; plane strides ≡ 8 (mod 32)
// give conflict-free mma A-fragment loads (bank = ch*8 + dx).
#define P_S0   1320          // 36x36=1296 pixels, padded
#define P_MID  1160          // 34x34=1156 pixels, padded
#define FC_S0_F   0                      // 16*1320 = 21120
#define FC_MID_F  21120                  // 16*1160 = 18560
#define FC_W1_F   39680                  // 9*16*20 = 2880
#define FC_W2_F   42560                  // 2880
#define FC_B1_F   45440                  // 16
#define FC_B2_F   45456                  // 16
#define FC_K2_F   45472                  // 16
#define FC_SMEM_F 45488
#define FC_SMEM_BYTES (FC_SMEM_F*4)

__global__ void __launch_bounds__(256)
fused_conv_kernel(const float* __restrict__ cw1, const float* __restrict__ cb1,
                  const float* __restrict__ cw2, const float* __restrict__ cb2,
                  float* __restrict__ out){
    extern __shared__ float smv[];
    float* sS0 = smv + FC_S0_F;
    float* sMid= smv + FC_MID_F;
    float* sW1 = smv + FC_W1_F;
    float* sW2 = smv + FC_W2_F;
    float* sB1 = smv + FC_B1_F;
    float* sB2 = smv + FC_B2_F;
    float* sK2 = smv + FC_K2_F;
    const int b  = blockIdx.z;
    const int y0 = blockIdx.y*32, x0 = blockIdx.x*32;
    const int t  = threadIdx.x;
    const int warp = t >> 5;
    const int lane = t & 31;
    const int qrow = lane >> 2;   // 0..7
    const int qcol = lane & 3;    // 0..3

    // --- constant-region skip ------------------------------------------------
    if (x0 >= y0 + 64){
        if (t < 16){
            float s = cb2[t];
            for (int c = 0; c < CH_; c++){
                float gg = gelu_f(cb1[c]);
                float ws = 0.f;
                #pragma unroll
                for (int kk = 0; kk < 9; kk++) ws += cw2[t*432 + c*9 + kk];
                s += ws*gg;
            }
            sK2[t] = s;
        }
        __syncthreads();
        const int ty = t >> 4, tx = t & 15;
        #pragma unroll
        for (int p = 0; p < 4; p++){
            const int y = y0 + 2*ty + (p >> 1);
            const int x = x0 + 2*tx + (p & 1);
            const float len = (float)(x - y);
            float4* op = reinterpret_cast<float4*>(&out[((y*N_ + x)*B_ + b)*O_]);
            #pragma unroll
            for (int o4 = 0; o4 < 4; o4++)
                op[o4] = make_float4(len*sK2[o4*4+0], len*sK2[o4*4+1],
                                     len*sK2[o4*4+2], len*sK2[o4*4+3]);
        }
        return;
    }

    // --- stage S0 window 16ch x 36x36 planar (origin y0-2, x0-2), tf32 -------
    for (int idx = t; idx < 16*1296; idx += 256){
        int ch = idx/1296, p = idx - ch*1296;
        int iy = p/36, ix = p - iy*36;
        int yy = y0 - 2 + iy, xx = x0 - 2 + ix;
        float v = 0.f;
        if (yy >= 0 && yy < N_ && xx >= 0 && xx < N_)
            v = g_S0[((b*O_ + ch)*N_ + yy)*N_ + xx];
        sS0[ch*P_S0 + p] = tf32f(v);
    }
    if (t < 16) sB2[t] = cb2[t];

    // plane pointers for A fragments (k = kb+qcol, kb in {0,8}; +4 for a2)
    const float* pS0a = sS0 + qcol*P_S0;
    const float* pS0b = sS0 + (qcol+4)*P_S0;
    const float* pS0c = sS0 + (qcol+8)*P_S0;
    const float* pS0d = sS0 + (qcol+12)*P_S0;
    const float* pMa = sMid + qcol*P_MID;
    const float* pMb = sMid + (qcol+4)*P_MID;
    const float* pMc = sMid + (qcol+8)*P_MID;
    const float* pMd = sMid + (qcol+12)*P_MID;

    float acc2[64];
    #pragma unroll
    for (int q = 0; q < 64; q++) acc2[q] = 0.f;

    for (int cg = 0; cg < 3; cg++){
        __syncthreads();   // prior conv2 reads of sMid/sW done; sS0 staged
        // stage weights for this group (tf32)
        for (int idx = t; idx < 2304; idx += 256){
            int k = idx & 15, n = (idx >> 4) & 15, kk = idx >> 8;
            sW1[kk*320 + n*20 + k] = tf32f(cw1[(cg*16 + n)*144 + k*9 + kk]);
            sW2[kk*320 + n*20 + k] = tf32f(cw2[n*432 + (cg*16 + k)*9 + kk]);
        }
        if (t < 16) sB1[t] = cb1[cg*16 + t];
        __syncthreads();

        // ---- conv1: Mid(r,c) = sum_taps sS0[r+ky][c+kx] @ W1tap  (N=16) ----
        for (int mt = warp; mt < 85; mt += 8){
            const int ri = mt/5, cbi = mt - ri*5;
            const int cb = (cbi < 4) ? cbi*8 : 26;
            float acc1[8];
            #pragma unroll
            for (int q = 0; q < 8; q++) acc1[q] = 0.f;
            const int p00 = (2*ri)*36 + cb + qrow;
            const float* w0 = sW1 + qrow*20 + qcol;
            #pragma unroll
            for (int ky = 0; ky < 3; ky++){
                #pragma unroll
                for (int kx = 0; kx < 3; kx++){
                    const int p = p00 + ky*36 + kx;
                    const float* w = w0 + (ky*3 + kx)*320;
                    // kstep 0 (k = qcol, qcol+4)
                    {
                        uint32_t a0 = __float_as_uint(pS0a[p]);
                        uint32_t a1 = __float_as_uint(pS0a[p + 36]);
                        uint32_t a2 = __float_as_uint(pS0b[p]);
                        uint32_t a3 = __float_as_uint(pS0b[p + 36]);
                        mma_tf32(acc1    , a0,a1,a2,a3,
                                 __float_as_uint(w[0]),   __float_as_uint(w[4]));
                        mma_tf32(acc1 + 4, a0,a1,a2,a3,
                                 __float_as_uint(w[160]), __float_as_uint(w[164]));
                    }
                    // kstep 1 (k = 8+qcol, 12+qcol)
                    {
                        uint32_t a0 = __float_as_uint(pS0c[p]);
                        uint32_t a1 = __float_as_uint(pS0c[p + 36]);
                        uint32_t a2 = __float_as_uint(pS0d[p]);
                        uint32_t a3 = __float_as_uint(pS0d[p + 36]);
                        mma_tf32(acc1    , a0,a1,a2,a3,
                                 __float_as_uint(w[8]),   __float_as_uint(w[12]));
                        mma_tf32(acc1 + 4, a0,a1,a2,a3,
                                 __float_as_uint(w[168]), __float_as_uint(w[172]));
                    }
                }
            }
            // store Mid (gelu + bias, tf32), planar
            const int pm = (2*ri)*34 + cb + qrow;
            #pragma unroll
            for (int nt = 0; nt < 2; nt++){
                const int ch0 = nt*8 + 2*qcol;
                const float bb0 = sB1[ch0], bb1 = sB1[ch0 + 1];
                sMid[ ch0   *P_MID + pm     ] = tf32f(gelu_f(acc1[nt*4+0] + bb0));
                sMid[(ch0+1)*P_MID + pm     ] = tf32f(gelu_f(acc1[nt*4+1] + bb1));
                sMid[ ch0   *P_MID + pm + 34] = tf32f(gelu_f(acc1[nt*4+2] + bb0));
                sMid[(ch0+1)*P_MID + pm + 34] = tf32f(gelu_f(acc1[nt*4+3] + bb1));
            }
        }
        __syncthreads();

        // ---- conv2: out += sum_taps Mid[u+ky][v+kx] @ W2tap  (N=16) ---------
        #pragma unroll
        for (int mi = 0; mi < 8; mi++){
            const int mt = mi*8 + warp;
            const int ui = mt >> 2, vb = (mt & 3)*8;
            const int p00 = (2*ui)*34 + vb + qrow;
            const float* w0 = sW2 + qrow*20 + qcol;
            float* ac = acc2 + mi*8;
            #pragma unroll
            for (int ky = 0; ky < 3; ky++){
                #pragma unroll
                for (int kx = 0; kx < 3; kx++){
                    const int p = p00 + ky*34 + kx;
                    const float* w = w0 + (ky*3 + kx)*320;
                    {
                        uint32_t a0 = __float_as_uint(pMa[p]);
                        uint32_t a1 = __float_as_uint(pMa[p + 34]);
                        uint32_t a2 = __float_as_uint(pMb[p]);
                        uint32_t a3 = __float_as_uint(pMb[p + 34]);
                        mma_tf32(ac    , a0,a1,a2,a3,
                                 __float_as_uint(w[0]),   __float_as_uint(w[4]));
                        mma_tf32(ac + 4, a0,a1,a2,a3,
                                 __float_as_uint(w[160]), __float_as_uint(w[164]));
                    }
                    {
                        uint32_t a0 = __float_as_uint(pMc[p]);
                        uint32_t a1 = __float_as_uint(pMc[p + 34]);
                        uint32_t a2 = __float_as_uint(pMd[p]);
                        uint32_t a3 = __float_as_uint(pMd[p + 34]);
                        mma_tf32(ac    , a0,a1,a2,a3,
                                 __float_as_uint(w[8]),   __float_as_uint(w[12]));
                        mma_tf32(ac + 4, a0,a1,a2,a3,
                                 __float_as_uint(w[168]), __float_as_uint(w[172]));
                    }
                }
            }
        }
    }

    // ---- epilogue: bias + |i-j| scale + permute to [y][x][b][16] ------------
    #pragma unroll
    for (int mi = 0; mi < 8; mi++){
        const int mt = mi*8 + warp;
        const int ui = mt >> 2, vb = (mt & 3)*8;
        const int x = x0 + vb + qrow;
        const float* ac = acc2 + mi*8;
        #pragma unroll
        for (int dy = 0; dy < 2; dy++){
            const int y = y0 + 2*ui + dy;
            int diff = y - x; if (diff < 0) diff = -diff; if (diff < 1) diff = 1;
            const float len = (float)diff;
            float* ob = &out[((y*N_ + x)*B_ + b)*O_];
            const int c0 = 2*qcol;
            const int e  = dy*2;
            *reinterpret_cast<float2*>(ob + c0) =
                make_float2(len*(ac[e    ] + sB2[c0    ]),
                            len*(ac[e + 1] + sB2[c0 + 1]));
            *reinterpret_cast<float2*>(ob + 8 + c0) =
                make_float2(len*(ac[4 + e    ] + sB2[8 + c0    ]),
                            len*(ac[4 + e + 1] + sB2[8 + c0 + 1]));
        }
    }
}

// ---------------- skip MLP ---------------------------------------------------
__global__ void skip_kernel(const float* __restrict__ x,
    const float* __restrict__ sw1, const float* __restrict__ sb1,
    const float* __restrict__ sw2, const float* __restrict__ sb2,
    const float* __restrict__ sw3, const float* __restrict__ sb3,
    float* __restrict__ out){
    __shared__ float sFeat[384];
    __shared__ float sH1[64];
    __shared__ float sH2[64];
    const int i = blockIdx.x, b = blockIdx.y;
    const int t = threadIdx.x;
    {
        float xa = x[(i*B_ + b)*D_ + t];
        float xb = x[((i+1)*B_ + b)*D_ + t];
        sFeat[t] = xa; sFeat[128 + t] = xb; sFeat[256 + t] = xa*xb;
    }
    __syncthreads();
    if (t < 64){
        float a = sb1[t];
        #pragma unroll 4
        for (int k = 0; k < 384; k++) a += sFeat[k]*sw1[t*384 + k];
        sH1[t] = gelu_f(a);
    }
    __syncthreads();
    if (t < 64){
        float a = sb2[t];
        #pragma unroll 4
        for (int k = 0; k < 64; k++) a += sH1[k]*sw2[t*64 + k];
        sH2[t] = gelu_f(a);
    }
    __syncthreads();
    if (t < 16){
        float a = sb3[t];
        #pragma unroll 4
        for (int k = 0; k < 64; k++) a += sH2[k]*sw3[t*64 + k];
        out[(i*B_ + b)*O_ + t] = a;
    }
}

// ---------------------------------------------------------------------------
extern "C" void kernel_launch(void* const* d_in, const int* in_sizes, int n_in,
                              void* d_out, int out_size){
    const float* x   = (const float*)d_in[0];
    const float* w1  = (const float*)d_in[1];
    const float* b1  = (const float*)d_in[2];
    const float* w2  = (const float*)d_in[3];
    const float* b2  = (const float*)d_in[4];
    const float* w3  = (const float*)d_in[5];
    const float* b3  = (const float*)d_in[6];
    const float* sw1 = (const float*)d_in[7];
    const float* sb1 = (const float*)d_in[8];
    const float* sw2 = (const float*)d_in[9];
    const float* sb2 = (const float*)d_in[10];
    const float* sw3 = (const float*)d_in[11];
    const float* sb3 = (const float*)d_in[12];
    const float* cw1 = (const float*)d_in[13];
    const float* cb1 = (const float*)d_in[14];
    const float* cw2 = (const float*)d_in[15];
    const float* cb2 = (const float*)d_in[16];
    float* out = (float*)d_out;

    const int pre_smem = 16512*4;
    cudaFuncSetAttribute(precompute_kernel, cudaFuncAttributeMaxDynamicSharedMemorySize, pre_smem);
    cudaFuncSetAttribute(pair_mlp_mma, cudaFuncAttributeMaxDynamicSharedMemorySize, PAIR_SMEM_BYTES);
    cudaFuncSetAttribute(fused_conv_kernel, cudaFuncAttributeMaxDynamicSharedMemorySize, FC_SMEM_BYTES);

    scan_kernel<<<256, 512>>>(x);
    zero_S0<<<2048, 256>>>();
    precompute_kernel<<<dim3(9, B_), 256, pre_smem>>>(x, w1);

    pair_mlp_mma<<<dim3(1280, 2), 256, PAIR_SMEM_BYTES>>>(x, w1, b1, w2, b2, w3, b3);

    fused_conv_kernel<<<dim3(16, 16, B_), 256, FC_SMEM_BYTES>>>(cw1, cb1, cw2, cb2, out);

    skip_kernel<<<dim3(N_-1, 2), 128>>>(x, sw1, sb1, sw2, sb2, sw3, sb3,
                                        out + (size_t)N_*N_*B_*O_);
}